// round 1
// baseline (speedup 1.0000x reference)
#include <cuda_runtime.h>
#include <cuda_bf16.h>
#include <math.h>

// ----------------------------------------------------------------------------
// Problem constants
// ----------------------------------------------------------------------------
#define NB 4
#define LM 1024
#define LS 1024
#define NE 768
#define NH 12
#define HD 64
#define HALF 512
#define NTOK (NB * LM)          // 4096
#define FCD (4 * NE)            // 3072
#define LN_EPS 1e-5f
#define FULLMASK 0xffffffffu

// ----------------------------------------------------------------------------
// Scratch (device globals -- no runtime allocation allowed)
// ----------------------------------------------------------------------------
__device__ float g_xn[NTOK * NE];   // LN(x) then reused as LN(x1) for MLP input
__device__ float g_sn[NTOK * NE];   // LN(mod_x)
__device__ float g_q [NTOK * NE];
__device__ float g_k [NTOK * NE];
__device__ float g_v [NTOK * NE];
__device__ float g_y [NTOK * NE];
__device__ float g_x1[NTOK * NE];   // x after attention residual
__device__ float g_h [NTOK * FCD]; // GELU(fc) activations
__device__ int   g_src[NB * LS];    // fused-embedding gather indices

// ----------------------------------------------------------------------------
// Kernel 1: stable argsort of mod_age + scatter bookkeeping.
// rank_j = #{i: a_i<a_j} + #{i<j: a_i==a_j}  (stable argsort)
// then serial prefix counts of 2s/3s in sorted order -> source row per slot.
// ----------------------------------------------------------------------------
__global__ void fuse_prep_kernel(const int* __restrict__ mod_idx,
                                 const float* __restrict__ mod_age)
{
    __shared__ float a[LS];
    __shared__ int   ord[LS];
    __shared__ int   sid[LS];
    int b = blockIdx.x;
    int j = threadIdx.x;
    a[j] = mod_age[b * LS + j];
    __syncthreads();
    float aj = a[j];
    int r = 0;
    for (int i = 0; i < LS; i++) {
        float ai = a[i];
        r += (ai < aj) || (ai == aj && i < j);
    }
    ord[r] = j;
    __syncthreads();
    sid[j] = mod_idx[b * LS + ord[j]];
    __syncthreads();
    if (j == 0) {
        int c2 = 0, c3 = 0;
        for (int t = 0; t < LS; t++) {
            int s = sid[t];
            int src;
            if (s == 2) {
                int row = (c2 < HALF) ? c2 : (HALF - 1);
                c2++;
                src = b * HALF + row;               // table 0 = mod2
            } else {
                int row = (c3 < HALF) ? c3 : (HALF - 1);
                c3++;
                src = (b * HALF + row) | (1 << 30); // table 1 = mod3
            }
            g_src[b * LS + t] = src;
        }
    }
}

// ----------------------------------------------------------------------------
// LayerNorm over 768-wide rows. 256 threads, 3 elements each.
// ----------------------------------------------------------------------------
__device__ __forceinline__ void ln_row_body(const float* __restrict__ p,
                                            float* __restrict__ o,
                                            const float* __restrict__ w,
                                            const float* __restrict__ bb)
{
    int t = threadIdx.x;
    float x0 = p[t], x1 = p[t + 256], x2 = p[t + 512];
    float s = x0 + x1 + x2;
    float q = x0 * x0 + x1 * x1 + x2 * x2;
    #pragma unroll
    for (int off = 16; off; off >>= 1) {
        s += __shfl_down_sync(FULLMASK, s, off);
        q += __shfl_down_sync(FULLMASK, q, off);
    }
    __shared__ float ss[8], sq[8];
    __shared__ float mr[2];
    int wid = t >> 5, lane = t & 31;
    if (lane == 0) { ss[wid] = s; sq[wid] = q; }
    __syncthreads();
    if (t == 0) {
        float S = 0.f, Q = 0.f;
        #pragma unroll
        for (int i = 0; i < 8; i++) { S += ss[i]; Q += sq[i]; }
        float mean = S * (1.f / NE);
        float var  = Q * (1.f / NE) - mean * mean;
        mr[0] = mean;
        mr[1] = rsqrtf(var + LN_EPS);
    }
    __syncthreads();
    float mean = mr[0], rstd = mr[1];
    o[t]       = (x0 - mean) * rstd * w[t]       + bb[t];
    o[t + 256] = (x1 - mean) * rstd * w[t + 256] + bb[t + 256];
    o[t + 512] = (x2 - mean) * rstd * w[t + 512] + bb[t + 512];
}

__global__ void ln_kernel(const float* __restrict__ in, float* __restrict__ out,
                          const float* __restrict__ w, const float* __restrict__ b)
{
    int row = blockIdx.x;
    ln_row_body(in + (size_t)row * NE, out + (size_t)row * NE, w, b);
}

// Gathered LN: mod_x row is a row of mod2_emb or mod3_emb.
__global__ void fuse_ln_kernel(const float* __restrict__ mod2,
                               const float* __restrict__ mod3,
                               float* __restrict__ out,
                               const float* __restrict__ w, const float* __restrict__ b)
{
    int row = blockIdx.x;
    int s = g_src[row];
    const float* tab = (s & (1 << 30)) ? mod3 : mod2;
    const float* p = tab + (size_t)(s & 0x3FFFFFFF) * NE;
    ln_row_body(p, out + (size_t)row * NE, w, b);
}

// ----------------------------------------------------------------------------
// SGEMM: C[M,N] = A[M,K] @ W[N,K]^T + bias[N]  (+epilogue)
// 128x128 tile, BK=8, 256 threads, 8x8 micro-tile.
// EPI: 0=none, 1=+residual, 2=gelu(exact)
// M % 128 == 0, N % 128 == 0, K % 8 == 0 (all true here).
// ----------------------------------------------------------------------------
template<int EPI>
__global__ void __launch_bounds__(256, 2)
sgemm_kernel(const float* __restrict__ A, const float* __restrict__ W,
             const float* __restrict__ bias, const float* __restrict__ res,
             float* __restrict__ C, int M, int N, int K)
{
    __shared__ float As[8][128];
    __shared__ float Ws[8][128];

    int tid = threadIdx.x;
    int m0 = blockIdx.y * 128;
    int n0 = blockIdx.x * 128;

    int lrow = tid >> 1;              // 0..127
    int lk   = (tid & 1) * 4;         // 0 or 4

    int tx = tid & 15;                // n dir
    int ty = tid >> 4;                // m dir

    float acc[8][8];
    #pragma unroll
    for (int i = 0; i < 8; i++)
        #pragma unroll
        for (int j = 0; j < 8; j++) acc[i][j] = 0.f;

    const float* Ap = A + (size_t)(m0 + lrow) * K + lk;
    const float* Wp = W + (size_t)(n0 + lrow) * K + lk;

    for (int kt = 0; kt < K; kt += 8) {
        float4 av = *(const float4*)(Ap + kt);
        float4 wv = *(const float4*)(Wp + kt);
        As[lk + 0][lrow] = av.x; As[lk + 1][lrow] = av.y;
        As[lk + 2][lrow] = av.z; As[lk + 3][lrow] = av.w;
        Ws[lk + 0][lrow] = wv.x; Ws[lk + 1][lrow] = wv.y;
        Ws[lk + 2][lrow] = wv.z; Ws[lk + 3][lrow] = wv.w;
        __syncthreads();

        #pragma unroll
        for (int kk = 0; kk < 8; kk++) {
            float af[8], wf[8];
            *(float4*)(af)     = *(const float4*)&As[kk][ty * 8];
            *(float4*)(af + 4) = *(const float4*)&As[kk][ty * 8 + 4];
            *(float4*)(wf)     = *(const float4*)&Ws[kk][tx * 8];
            *(float4*)(wf + 4) = *(const float4*)&Ws[kk][tx * 8 + 4];
            #pragma unroll
            for (int i = 0; i < 8; i++)
                #pragma unroll
                for (int j = 0; j < 8; j++)
                    acc[i][j] = fmaf(af[i], wf[j], acc[i][j]);
        }
        __syncthreads();
    }

    #pragma unroll
    for (int i = 0; i < 8; i++) {
        int m = m0 + ty * 8 + i;
        #pragma unroll
        for (int j = 0; j < 8; j++) {
            int n = n0 + tx * 8 + j;
            float c = acc[i][j] + bias[n];
            if (EPI == 1) c += res[(size_t)m * N + n];
            if (EPI == 2) c = 0.5f * c * (1.f + erff(c * 0.70710678118654752f));
            C[(size_t)m * N + n] = c;
        }
    }
}

// ----------------------------------------------------------------------------
// Attention: per (b,h), prefix-masked flash-style.
// Block = 8 warps, warp per q-row. K/V streamed in 64-key tiles via smem.
// kmax(q) via binary search on sorted mod_age.
// ----------------------------------------------------------------------------
__global__ void __launch_bounds__(256)
attn_kernel(const float* __restrict__ Q, const float* __restrict__ Kmat,
            const float* __restrict__ V, const float* __restrict__ age,
            const float* __restrict__ mage, float* __restrict__ Y)
{
    int b = blockIdx.z, h = blockIdx.y;
    int qbase = blockIdx.x * 8;
    int tid = threadIdx.x, wid = tid >> 5, lane = tid & 31;
    int qrow = qbase + wid;

    __shared__ float KT[64][64];   // [d][key]
    __shared__ float Vs[64][64];   // [key][d]
    __shared__ int   s_kmax[8];

    // per-row valid-key count (mod_age sorted ascending)
    float a = age[b * LM + qrow];
    int km = 0;
    if (lane == 0) {
        const float* ma = mage + b * LS;
        int lo = 0, hi = LS;
        while (lo < hi) {
            int mid = (lo + hi) >> 1;
            if (ma[mid] <= a) lo = mid + 1; else hi = mid;
        }
        km = lo;
        s_kmax[wid] = lo;
    }
    km = __shfl_sync(FULLMASK, km, 0);
    __syncthreads();
    int kmax_max = 0;
    #pragma unroll
    for (int i = 0; i < 8; i++) kmax_max = max(kmax_max, s_kmax[i]);

    const float* qp = Q + (size_t)(b * LM + qrow) * NE + h * HD;
    float q0r = qp[lane], q1r = qp[lane + 32];

    float m = -INFINITY, l = 0.f, y0 = 0.f, y1 = 0.f;

    for (int kt = 0; kt < kmax_max; kt += 64) {
        // cooperative K (transposed) + V tile load
        {
            int key = tid >> 2;
            int dbase = (tid & 3) * 16;
            const float* kp = Kmat + (size_t)(b * LS + kt + key) * NE + h * HD + dbase;
            const float* vp = V    + (size_t)(b * LS + kt + key) * NE + h * HD + dbase;
            #pragma unroll
            for (int i = 0; i < 4; i++) {
                float4 kv = *(const float4*)(kp + i * 4);
                KT[dbase + i * 4 + 0][key] = kv.x;
                KT[dbase + i * 4 + 1][key] = kv.y;
                KT[dbase + i * 4 + 2][key] = kv.z;
                KT[dbase + i * 4 + 3][key] = kv.w;
                *(float4*)&Vs[key][dbase + i * 4] = *(const float4*)(vp + i * 4);
            }
        }
        __syncthreads();

        if (kt < km) {
            // scores for keys kt+2*lane, kt+2*lane+1
            float s0 = 0.f, s1 = 0.f;
            #pragma unroll
            for (int d = 0; d < 64; d++) {
                float qd = (d < 32) ? __shfl_sync(FULLMASK, q0r, d)
                                    : __shfl_sync(FULLMASK, q1r, d - 32);
                float2 kk = *(const float2*)&KT[d][2 * lane];
                s0 = fmaf(qd, kk.x, s0);
                s1 = fmaf(qd, kk.y, s1);
            }
            s0 *= 0.125f; s1 *= 0.125f;
            int kg = kt + 2 * lane;
            if (kg     >= km) s0 = -INFINITY;
            if (kg + 1 >= km) s1 = -INFINITY;

            float mt = fmaxf(s0, s1);
            #pragma unroll
            for (int o = 16; o; o >>= 1)
                mt = fmaxf(mt, __shfl_xor_sync(FULLMASK, mt, o));
            float mnew = fmaxf(m, mt);
            float corr = __expf(m - mnew);
            float p0 = __expf(s0 - mnew);
            float p1 = __expf(s1 - mnew);
            float ps = p0 + p1;
            #pragma unroll
            for (int o = 16; o; o >>= 1)
                ps += __shfl_xor_sync(FULLMASK, ps, o);
            l = l * corr + ps;
            y0 *= corr; y1 *= corr;
            m = mnew;

            #pragma unroll
            for (int k2 = 0; k2 < 32; k2++) {
                float pa = __shfl_sync(FULLMASK, p0, k2);
                float pb = __shfl_sync(FULLMASK, p1, k2);
                float2 va = *(const float2*)&Vs[2 * k2][2 * lane];
                float2 vb = *(const float2*)&Vs[2 * k2 + 1][2 * lane];
                y0 = fmaf(pa, va.x, y0); y0 = fmaf(pb, vb.x, y0);
                y1 = fmaf(pa, va.y, y1); y1 = fmaf(pb, vb.y, y1);
            }
        }
        __syncthreads();
    }

    float inv = (l > 0.f) ? (1.f / l) : 0.f;
    float* yp = Y + (size_t)(b * LM + qrow) * NE + h * HD;
    yp[2 * lane]     = y0 * inv;
    yp[2 * lane + 1] = y1 * inv;
}

// ----------------------------------------------------------------------------
// Launch
// ----------------------------------------------------------------------------
extern "C" void kernel_launch(void* const* d_in, const int* in_sizes, int n_in,
                              void* d_out, int out_size)
{
    const float* x        = (const float*)d_in[0];
    const float* age      = (const float*)d_in[1];
    const int*   mod_idx  = (const int*)  d_in[2];
    const float* mod_age  = (const float*)d_in[3];
    const float* mod2     = (const float*)d_in[4];
    const float* mod3     = (const float*)d_in[5];
    const float* ln0_w    = (const float*)d_in[6];
    const float* ln0_b    = (const float*)d_in[7];
    const float* ln1_w    = (const float*)d_in[8];
    const float* ln1_b    = (const float*)d_in[9];
    const float* ln2_w    = (const float*)d_in[10];
    const float* ln2_b    = (const float*)d_in[11];
    const float* q_w      = (const float*)d_in[12];
    const float* q_b      = (const float*)d_in[13];
    const float* k_w      = (const float*)d_in[14];
    const float* k_b      = (const float*)d_in[15];
    const float* v_w      = (const float*)d_in[16];
    const float* v_b      = (const float*)d_in[17];
    const float* c_w      = (const float*)d_in[18];
    const float* c_b      = (const float*)d_in[19];
    const float* fc_w     = (const float*)d_in[20];
    const float* fc_b     = (const float*)d_in[21];
    const float* proj_w   = (const float*)d_in[22];
    const float* proj_b   = (const float*)d_in[23];
    float* out = (float*)d_out;

    float *p_xn, *p_sn, *p_q, *p_k, *p_v, *p_y, *p_x1, *p_h;
    cudaGetSymbolAddress((void**)&p_xn, g_xn);
    cudaGetSymbolAddress((void**)&p_sn, g_sn);
    cudaGetSymbolAddress((void**)&p_q,  g_q);
    cudaGetSymbolAddress((void**)&p_k,  g_k);
    cudaGetSymbolAddress((void**)&p_v,  g_v);
    cudaGetSymbolAddress((void**)&p_y,  g_y);
    cudaGetSymbolAddress((void**)&p_x1, g_x1);
    cudaGetSymbolAddress((void**)&p_h,  g_h);

    // 1. modality fuse bookkeeping
    fuse_prep_kernel<<<NB, LS>>>(mod_idx, mod_age);

    // 2. LayerNorms
    ln_kernel<<<NTOK, 256>>>(x, p_xn, ln1_w, ln1_b);
    fuse_ln_kernel<<<NTOK, 256>>>(mod2, mod3, p_sn, ln0_w, ln0_b);

    // 3. Q/K/V projections
    dim3 g768(NE / 128, NTOK / 128);
    sgemm_kernel<0><<<g768, 256>>>(p_xn, q_w, q_b, nullptr, p_q, NTOK, NE, NE);
    sgemm_kernel<0><<<g768, 256>>>(p_sn, k_w, k_b, nullptr, p_k, NTOK, NE, NE);
    sgemm_kernel<0><<<g768, 256>>>(p_sn, v_w, v_b, nullptr, p_v, NTOK, NE, NE);

    // 4. attention
    dim3 ga(LM / 8, NH, NB);
    attn_kernel<<<ga, 256>>>(p_q, p_k, p_v, age, mod_age, p_y);

    // 5. output projection + residual -> x1
    sgemm_kernel<1><<<g768, 256>>>(p_y, c_w, c_b, x, p_x1, NTOK, NE, NE);

    // 6. MLP: LN -> fc+gelu -> proj + residual -> out
    ln_kernel<<<NTOK, 256>>>(p_x1, p_xn, ln2_w, ln2_b);
    dim3 gfc(FCD / 128, NTOK / 128);
    sgemm_kernel<2><<<gfc, 256>>>(p_xn, fc_w, fc_b, nullptr, p_h, NTOK, FCD, NE);
    sgemm_kernel<1><<<g768, 256>>>(p_h, proj_w, proj_b, p_x1, out, NTOK, NE, FCD);
}

// round 6
// speedup vs baseline: 1.1754x; 1.1754x over previous
#include <cuda_runtime.h>
#include <cuda_bf16.h>
#include <math.h>
#include <stdint.h>

// ----------------------------------------------------------------------------
// Problem constants
// ----------------------------------------------------------------------------
#define NB 4
#define LM 1024
#define LS 1024
#define NE 768
#define NH 12
#define HD 64
#define HALF 512
#define NTOK (NB * LM)          // 4096
#define FCD (4 * NE)            // 3072
#define LN_EPS 1e-5f
#define FULLMASK 0xffffffffu

// ----------------------------------------------------------------------------
// Scratch (device globals -- no runtime allocation allowed)
// ----------------------------------------------------------------------------
__device__ float g_q  [NTOK * NE];
__device__ float g_k  [NTOK * NE];
__device__ float g_v  [NTOK * NE];
__device__ float g_x1 [NTOK * NE];
__device__ float g_xn [NTOK * NE];   // tf32-rounded LN outputs
__device__ float g_sn [NTOK * NE];
__device__ float g_y  [NTOK * NE];   // tf32-rounded attention out
__device__ float g_h  [NTOK * FCD]; // tf32-rounded GELU activations
__device__ float g_wq [NE * NE];     // tf32-rounded weights
__device__ float g_wk [NE * NE];
__device__ float g_wv [NE * NE];
__device__ float g_wc [NE * NE];
__device__ float g_wfc[FCD * NE];
__device__ float g_wpr[NE * FCD];
__device__ int   g_src[NB * LS];

__device__ __forceinline__ uint32_t smem_u32(const void* p) {
    return (uint32_t)__cvta_generic_to_shared(p);
}
__device__ __forceinline__ float tf32r(float x) {
    uint32_t u;
    asm("cvt.rna.tf32.f32 %0, %1;" : "=r"(u) : "f"(x));
    return __uint_as_float(u);
}

// ----------------------------------------------------------------------------
// fp32 -> tf32-rounded fp32 (n divisible by 512)
// ----------------------------------------------------------------------------
__global__ void f2tf_kernel(const float* __restrict__ in, float* __restrict__ out, int n) {
    int i = (blockIdx.x * 256 + threadIdx.x) * 2;
    if (i < n) {
        float2 v = *(const float2*)(in + i);
        v.x = tf32r(v.x); v.y = tf32r(v.y);
        *(float2*)(out + i) = v;
    }
}

// ----------------------------------------------------------------------------
// Kernel: stable argsort of mod_age + scatter bookkeeping
// ----------------------------------------------------------------------------
__global__ void fuse_prep_kernel(const int* __restrict__ mod_idx,
                                 const float* __restrict__ mod_age)
{
    __shared__ float a[LS];
    __shared__ int   ord[LS];
    __shared__ int   sid[LS];
    int b = blockIdx.x;
    int j = threadIdx.x;
    a[j] = mod_age[b * LS + j];
    __syncthreads();
    float aj = a[j];
    int r = 0;
    for (int i = 0; i < LS; i++) {
        float ai = a[i];
        r += (ai < aj) || (ai == aj && i < j);
    }
    ord[r] = j;
    __syncthreads();
    sid[j] = mod_idx[b * LS + ord[j]];
    __syncthreads();
    if (j == 0) {
        int c2 = 0, c3 = 0;
        for (int t = 0; t < LS; t++) {
            int s = sid[t];
            int src;
            if (s == 2) {
                int row = (c2 < HALF) ? c2 : (HALF - 1);
                c2++;
                src = b * HALF + row;
            } else {
                int row = (c3 < HALF) ? c3 : (HALF - 1);
                c3++;
                src = (b * HALF + row) | (1 << 30);
            }
            g_src[b * LS + t] = src;
        }
    }
}

// ----------------------------------------------------------------------------
// LayerNorm over 768-wide rows -> tf32-rounded fp32. 256 threads, 3 elems each.
// ----------------------------------------------------------------------------
__device__ __forceinline__ void ln_row_body(const float* __restrict__ p,
                                            float* __restrict__ o,
                                            const float* __restrict__ w,
                                            const float* __restrict__ bb)
{
    int t = threadIdx.x;
    float x0 = p[t], x1 = p[t + 256], x2 = p[t + 512];
    float s = x0 + x1 + x2;
    float q = x0 * x0 + x1 * x1 + x2 * x2;
    #pragma unroll
    for (int off = 16; off; off >>= 1) {
        s += __shfl_down_sync(FULLMASK, s, off);
        q += __shfl_down_sync(FULLMASK, q, off);
    }
    __shared__ float ss[8], sq[8];
    __shared__ float mr[2];
    int wid = t >> 5, lane = t & 31;
    if (lane == 0) { ss[wid] = s; sq[wid] = q; }
    __syncthreads();
    if (t == 0) {
        float S = 0.f, Q = 0.f;
        #pragma unroll
        for (int i = 0; i < 8; i++) { S += ss[i]; Q += sq[i]; }
        float mean = S * (1.f / NE);
        float var  = Q * (1.f / NE) - mean * mean;
        mr[0] = mean;
        mr[1] = rsqrtf(var + LN_EPS);
    }
    __syncthreads();
    float mean = mr[0], rstd = mr[1];
    o[t]       = tf32r((x0 - mean) * rstd * w[t]       + bb[t]);
    o[t + 256] = tf32r((x1 - mean) * rstd * w[t + 256] + bb[t + 256]);
    o[t + 512] = tf32r((x2 - mean) * rstd * w[t + 512] + bb[t + 512]);
}

__global__ void ln_kernel(const float* __restrict__ in, float* __restrict__ out,
                          const float* __restrict__ w, const float* __restrict__ b)
{
    int row = blockIdx.x;
    ln_row_body(in + (size_t)row * NE, out + (size_t)row * NE, w, b);
}

__global__ void fuse_ln_kernel(const float* __restrict__ mod2,
                               const float* __restrict__ mod3,
                               float* __restrict__ out,
                               const float* __restrict__ w, const float* __restrict__ b)
{
    int row = blockIdx.x;
    int s = g_src[row];
    const float* tab = (s & (1 << 30)) ? mod3 : mod2;
    const float* p = tab + (size_t)(s & 0x3FFFFFFF) * NE;
    ln_row_body(p, out + (size_t)row * NE, w, b);
}

// ----------------------------------------------------------------------------
// TF32 HMMA GEMM: C[M,N] = A[M,K] @ W[N,K]^T + bias[N]  (+epilogue)
// 128x128x16 tile, 256 threads, warp tile 32x64, mma.m16n8k8.tf32, cp.async
// double buffer, PAD=20 floats -> all fragment LDS conflict-free.
// A and W must be tf32-pre-rounded fp32.
// EPI: 0 = fp32 out; 1 = fp32 out + residual; 2 = gelu -> tf32-rounded fp32
// ----------------------------------------------------------------------------
#define BM 128
#define BN 128
#define BK 16
#define PAD 20

template<int EPI>
__global__ void __launch_bounds__(256, 2)
tgemm_kernel(const float* __restrict__ A, const float* __restrict__ W,
             const float* __restrict__ bias, const float* __restrict__ res,
             float* __restrict__ Cout, int M, int N, int K)
{
    __shared__ float sA[2][BM * PAD];
    __shared__ float sB[2][BN * PAD];

    const int tid = threadIdx.x;
    const int lane = tid & 31, wid = tid >> 5;
    const int warp_m = wid & 3, warp_n = wid >> 2;   // 4 x 2 warp grid
    const int m0 = blockIdx.y * BM, n0 = blockIdx.x * BN;

    float acc[2][8][4];
    #pragma unroll
    for (int im = 0; im < 2; im++)
        #pragma unroll
        for (int jn = 0; jn < 8; jn++)
            #pragma unroll
            for (int r = 0; r < 4; r++) acc[im][jn][r] = 0.f;

    const int ld_row = tid >> 2;          // 0..63 (x2 halves)
    const int ld_sub = tid & 3;           // 16B chunk (4 floats) in row

    const int nk = K / BK;

    auto load_stage = [&](int s, int kt) {
        const float* Ag = A + (size_t)m0 * K + kt * BK;
        const float* Bg = W + (size_t)n0 * K + kt * BK;
        #pragma unroll
        for (int i = 0; i < 2; i++) {
            int row = ld_row + i * 64;
            uint32_t da = smem_u32(&sA[s][row * PAD + ld_sub * 4]);
            const void* ga = Ag + (size_t)row * K + ld_sub * 4;
            asm volatile("cp.async.cg.shared.global [%0], [%1], 16;" :: "r"(da), "l"(ga));
            uint32_t db = smem_u32(&sB[s][row * PAD + ld_sub * 4]);
            const void* gb = Bg + (size_t)row * K + ld_sub * 4;
            asm volatile("cp.async.cg.shared.global [%0], [%1], 16;" :: "r"(db), "l"(gb));
        }
        asm volatile("cp.async.commit_group;" ::: "memory");
    };

    load_stage(0, 0);

    const int a_r = lane >> 2;      // 0..7
    const int a_c = lane & 3;       // 0..3

    for (int kt = 0; kt < nk; kt++) {
        const int buf = kt & 1;
        if (kt + 1 < nk) {
            load_stage(buf ^ 1, kt + 1);
            asm volatile("cp.async.wait_group 1;" ::: "memory");
        } else {
            asm volatile("cp.async.wait_group 0;" ::: "memory");
        }
        __syncthreads();

        const uint32_t* uA = (const uint32_t*)sA[buf];
        const uint32_t* uB = (const uint32_t*)sB[buf];

        #pragma unroll
        for (int ks = 0; ks < 2; ks++) {
            const int kof = ks * 8 + a_c;
            // A fragments: 2 x (16x8)
            uint32_t af[2][4];
            #pragma unroll
            for (int im = 0; im < 2; im++) {
                int br = warp_m * 32 + im * 16 + a_r;
                af[im][0] = uA[br * PAD + kof];
                af[im][1] = uA[(br + 8) * PAD + kof];
                af[im][2] = uA[br * PAD + kof + 4];
                af[im][3] = uA[(br + 8) * PAD + kof + 4];
            }
            // B fragments: 8 x (8x8)
            uint32_t bf[8][2];
            #pragma unroll
            for (int jn = 0; jn < 8; jn++) {
                int nn = warp_n * 64 + jn * 8 + a_r;
                bf[jn][0] = uB[nn * PAD + kof];
                bf[jn][1] = uB[nn * PAD + kof + 4];
            }
            #pragma unroll
            for (int im = 0; im < 2; im++)
                #pragma unroll
                for (int jn = 0; jn < 8; jn++) {
                    asm volatile(
                        "mma.sync.aligned.m16n8k8.row.col.f32.tf32.tf32.f32 "
                        "{%0,%1,%2,%3}, {%4,%5,%6,%7}, {%8,%9}, {%0,%1,%2,%3};"
                        : "+f"(acc[im][jn][0]), "+f"(acc[im][jn][1]),
                          "+f"(acc[im][jn][2]), "+f"(acc[im][jn][3])
                        : "r"(af[im][0]), "r"(af[im][1]), "r"(af[im][2]), "r"(af[im][3]),
                          "r"(bf[jn][0]), "r"(bf[jn][1]));
                }
        }
        __syncthreads();
    }

    // --- epilogue ---
    #pragma unroll
    for (int im = 0; im < 2; im++) {
        #pragma unroll
        for (int jn = 0; jn < 8; jn++) {
            int n = n0 + warp_n * 64 + jn * 8 + (lane & 3) * 2;
            float b0 = bias[n], b1 = bias[n + 1];
            #pragma unroll
            for (int rp = 0; rp < 2; rp++) {
                int m = m0 + warp_m * 32 + im * 16 + (lane >> 2) + 8 * rp;
                float v0 = acc[im][jn][2 * rp]     + b0;
                float v1 = acc[im][jn][2 * rp + 1] + b1;
                if (EPI == 1) {
                    const float* rr = res + (size_t)m * N + n;
                    v0 += rr[0]; v1 += rr[1];
                }
                if (EPI == 2) {
                    v0 = 0.5f * v0 * (1.f + erff(v0 * 0.70710678118654752f));
                    v1 = 0.5f * v1 * (1.f + erff(v1 * 0.70710678118654752f));
                    v0 = tf32r(v0); v1 = tf32r(v1);
                }
                *(float2*)(Cout + (size_t)m * N + n) = make_float2(v0, v1);
            }
        }
    }
}

// ----------------------------------------------------------------------------
// Attention: per (b,h), prefix-masked flash-style. Warp per q-row.
// q and p broadcast via smem. Output tf32-rounded fp32.
// ----------------------------------------------------------------------------
__global__ void __launch_bounds__(256)
attn_kernel(const float* __restrict__ Q, const float* __restrict__ Kmat,
            const float* __restrict__ V, const float* __restrict__ age,
            const float* __restrict__ mage, float* __restrict__ Y)
{
    int b = blockIdx.z, h = blockIdx.y;
    int qbase = blockIdx.x * 8;
    int tid = threadIdx.x, wid = tid >> 5, lane = tid & 31;
    int qrow = qbase + wid;

    __shared__ float KT[64][64];   // [d][key]
    __shared__ float Vs[64][64];   // [key][d]
    __shared__ float Qs[8][64];
    __shared__ float Ps[8][64];
    __shared__ int   s_kmax[8];

    float a = age[b * LM + qrow];
    int km = 0;
    if (lane == 0) {
        const float* ma = mage + b * LS;
        int lo = 0, hi = LS;
        while (lo < hi) {
            int mid = (lo + hi) >> 1;
            if (ma[mid] <= a) lo = mid + 1; else hi = mid;
        }
        km = lo;
        s_kmax[wid] = lo;
    }
    km = __shfl_sync(FULLMASK, km, 0);

    const float* qp = Q + (size_t)(b * LM + qrow) * NE + h * HD;
    Qs[wid][lane]      = qp[lane];
    Qs[wid][lane + 32] = qp[lane + 32];
    __syncthreads();
    int kmax_max = 0;
    #pragma unroll
    for (int i = 0; i < 8; i++) kmax_max = max(kmax_max, s_kmax[i]);

    float m = -INFINITY, l = 0.f, y0 = 0.f, y1 = 0.f;

    for (int kt = 0; kt < kmax_max; kt += 64) {
        {
            int key = tid >> 2;
            int dbase = (tid & 3) * 16;
            const float* kp = Kmat + (size_t)(b * LS + kt + key) * NE + h * HD + dbase;
            const float* vp = V    + (size_t)(b * LS + kt + key) * NE + h * HD + dbase;
            #pragma unroll
            for (int i = 0; i < 4; i++) {
                float4 kv = *(const float4*)(kp + i * 4);
                KT[dbase + i * 4 + 0][key] = kv.x;
                KT[dbase + i * 4 + 1][key] = kv.y;
                KT[dbase + i * 4 + 2][key] = kv.z;
                KT[dbase + i * 4 + 3][key] = kv.w;
                *(float4*)&Vs[key][dbase + i * 4] = *(const float4*)(vp + i * 4);
            }
        }
        __syncthreads();

        if (kt < km) {
            float s0 = 0.f, s1 = 0.f;
            #pragma unroll
            for (int d = 0; d < 64; d++) {
                float qd = Qs[wid][d];
                float2 kk = *(const float2*)&KT[d][2 * lane];
                s0 = fmaf(qd, kk.x, s0);
                s1 = fmaf(qd, kk.y, s1);
            }
            s0 *= 0.125f; s1 *= 0.125f;
            int kg = kt + 2 * lane;
            if (kg     >= km) s0 = -INFINITY;
            if (kg + 1 >= km) s1 = -INFINITY;

            float mt = fmaxf(s0, s1);
            #pragma unroll
            for (int o = 16; o; o >>= 1)
                mt = fmaxf(mt, __shfl_xor_sync(FULLMASK, mt, o));
            float mnew = fmaxf(m, mt);
            float corr = __expf(m - mnew);
            float p0 = __expf(s0 - mnew);
            float p1 = __expf(s1 - mnew);
            float ps = p0 + p1;
            #pragma unroll
            for (int o = 16; o; o >>= 1)
                ps += __shfl_xor_sync(FULLMASK, ps, o);
            l = l * corr + ps;
            y0 *= corr; y1 *= corr;
            m = mnew;

            Ps[wid][2 * lane]     = p0;
            Ps[wid][2 * lane + 1] = p1;
            __syncwarp();
            #pragma unroll
            for (int k2 = 0; k2 < 64; k2++) {
                float pk = Ps[wid][k2];
                float2 vv = *(const float2*)&Vs[k2][2 * lane];
                y0 = fmaf(pk, vv.x, y0);
                y1 = fmaf(pk, vv.y, y1);
            }
        }
        __syncthreads();
    }

    float inv = (l > 0.f) ? (1.f / l) : 0.f;
    float* yp = Y + (size_t)(b * LM + qrow) * NE + h * HD;
    yp[2 * lane]     = tf32r(y0 * inv);
    yp[2 * lane + 1] = tf32r(y1 * inv);
}

// ----------------------------------------------------------------------------
// Launch
// ----------------------------------------------------------------------------
extern "C" void kernel_launch(void* const* d_in, const int* in_sizes, int n_in,
                              void* d_out, int out_size)
{
    const float* x        = (const float*)d_in[0];
    const float* age      = (const float*)d_in[1];
    const int*   mod_idx  = (const int*)  d_in[2];
    const float* mod_age  = (const float*)d_in[3];
    const float* mod2     = (const float*)d_in[4];
    const float* mod3     = (const float*)d_in[5];
    const float* ln0_w    = (const float*)d_in[6];
    const float* ln0_b    = (const float*)d_in[7];
    const float* ln1_w    = (const float*)d_in[8];
    const float* ln1_b    = (const float*)d_in[9];
    const float* ln2_w    = (const float*)d_in[10];
    const float* ln2_b    = (const float*)d_in[11];
    const float* q_w      = (const float*)d_in[12];
    const float* q_b      = (const float*)d_in[13];
    const float* k_w      = (const float*)d_in[14];
    const float* k_b      = (const float*)d_in[15];
    const float* v_w      = (const float*)d_in[16];
    const float* v_b      = (const float*)d_in[17];
    const float* c_w      = (const float*)d_in[18];
    const float* c_b      = (const float*)d_in[19];
    const float* fc_w     = (const float*)d_in[20];
    const float* fc_b     = (const float*)d_in[21];
    const float* proj_w   = (const float*)d_in[22];
    const float* proj_b   = (const float*)d_in[23];
    float* out = (float*)d_out;

    float *p_q, *p_k, *p_v, *p_x1, *p_xn, *p_sn, *p_y, *p_h;
    float *p_wq, *p_wk, *p_wv, *p_wc, *p_wfc, *p_wpr;
    cudaGetSymbolAddress((void**)&p_q,   g_q);
    cudaGetSymbolAddress((void**)&p_k,   g_k);
    cudaGetSymbolAddress((void**)&p_v,   g_v);
    cudaGetSymbolAddress((void**)&p_x1,  g_x1);
    cudaGetSymbolAddress((void**)&p_xn,  g_xn);
    cudaGetSymbolAddress((void**)&p_sn,  g_sn);
    cudaGetSymbolAddress((void**)&p_y,   g_y);
    cudaGetSymbolAddress((void**)&p_h,   g_h);
    cudaGetSymbolAddress((void**)&p_wq,  g_wq);
    cudaGetSymbolAddress((void**)&p_wk,  g_wk);
    cudaGetSymbolAddress((void**)&p_wv,  g_wv);
    cudaGetSymbolAddress((void**)&p_wc,  g_wc);
    cudaGetSymbolAddress((void**)&p_wfc, g_wfc);
    cudaGetSymbolAddress((void**)&p_wpr, g_wpr);

    // 0. weight pre-rounding to tf32
    const int WSQ = NE * NE, WFC = FCD * NE;
    f2tf_kernel<<<WSQ / 512, 256>>>(q_w,    p_wq,  WSQ);
    f2tf_kernel<<<WSQ / 512, 256>>>(k_w,    p_wk,  WSQ);
    f2tf_kernel<<<WSQ / 512, 256>>>(v_w,    p_wv,  WSQ);
    f2tf_kernel<<<WSQ / 512, 256>>>(c_w,    p_wc,  WSQ);
    f2tf_kernel<<<WFC / 512, 256>>>(fc_w,   p_wfc, WFC);
    f2tf_kernel<<<WFC / 512, 256>>>(proj_w, p_wpr, WFC);

    // 1. modality fuse bookkeeping
    fuse_prep_kernel<<<NB, LS>>>(mod_idx, mod_age);

    // 2. LayerNorms -> tf32-rounded fp32
    ln_kernel<<<NTOK, 256>>>(x, p_xn, ln1_w, ln1_b);
    fuse_ln_kernel<<<NTOK, 256>>>(mod2, mod3, p_sn, ln0_w, ln0_b);

    // 3. Q/K/V projections (tf32 HMMA, fp32 out)
    dim3 g768(NE / 128, NTOK / 128);
    tgemm_kernel<0><<<g768, 256>>>(p_xn, p_wq, q_b, nullptr, p_q, NTOK, NE, NE);
    tgemm_kernel<0><<<g768, 256>>>(p_sn, p_wk, k_b, nullptr, p_k, NTOK, NE, NE);
    tgemm_kernel<0><<<g768, 256>>>(p_sn, p_wv, v_b, nullptr, p_v, NTOK, NE, NE);

    // 4. attention -> tf32-rounded y
    dim3 ga(LM / 8, NH, NB);
    attn_kernel<<<ga, 256>>>(p_q, p_k, p_v, age, mod_age, p_y);

    // 5. output projection + residual -> x1 (fp32)
    tgemm_kernel<1><<<g768, 256>>>(p_y, p_wc, c_b, x, p_x1, NTOK, NE, NE);

    // 6. MLP
    ln_kernel<<<NTOK, 256>>>(p_x1, p_xn, ln2_w, ln2_b);
    dim3 gfc(FCD / 128, NTOK / 128);
    tgemm_kernel<2><<<gfc, 256>>>(p_xn, p_wfc, fc_b, nullptr, p_h, NTOK, FCD, NE);
    tgemm_kernel<1><<<g768, 256>>>(p_h, p_wpr, proj_b, p_x1, out, NTOK, NE, FCD);
}

// round 7
// speedup vs baseline: 1.4465x; 1.2307x over previous
#include <cuda_runtime.h>
#include <cuda_fp16.h>
#include <math.h>
#include <stdint.h>

// ----------------------------------------------------------------------------
// Problem constants
// ----------------------------------------------------------------------------
#define NB 4
#define LM 1024
#define LS 1024
#define NE 768
#define NH 12
#define HD 64
#define HALF 512
#define NTOK (NB * LM)          // 4096
#define FCD (4 * NE)            // 3072
#define LN_EPS 1e-5f
#define FULLMASK 0xffffffffu

// ----------------------------------------------------------------------------
// Scratch (device globals -- no runtime allocation allowed)
// ----------------------------------------------------------------------------
__device__ float g_q [NTOK * NE];
__device__ float g_k [NTOK * NE];
__device__ float g_v [NTOK * NE];
__device__ float g_x1[NTOK * NE];
__device__ __half g_xnh[NTOK * NE];   // LN outputs (fp16)
__device__ __half g_snh[NTOK * NE];
__device__ __half g_yh [NTOK * NE];   // attention out (fp16)
__device__ __half g_hh [NTOK * FCD]; // GELU activations (fp16)
__device__ __half g_wq [NE * NE];     // weights (fp16)
__device__ __half g_wk [NE * NE];
__device__ __half g_wv [NE * NE];
__device__ __half g_wc [NE * NE];
__device__ __half g_wfc[FCD * NE];
__device__ __half g_wpr[NE * FCD];
__device__ int g_src[NB * LS];

__device__ __forceinline__ uint32_t smem_u32(const void* p) {
    return (uint32_t)__cvta_generic_to_shared(p);
}

// ----------------------------------------------------------------------------
// fp32 -> fp16 conversion (n divisible by 512)
// ----------------------------------------------------------------------------
__global__ void f2h_kernel(const float* __restrict__ in, __half* __restrict__ out, int n) {
    int i = (blockIdx.x * 256 + threadIdx.x) * 2;
    if (i < n) {
        float2 v = *(const float2*)(in + i);
        *(__half2*)(out + i) = __floats2half2_rn(v.x, v.y);
    }
}

// ----------------------------------------------------------------------------
// Kernel: stable argsort of mod_age + scatter bookkeeping
// ----------------------------------------------------------------------------
__global__ void fuse_prep_kernel(const int* __restrict__ mod_idx,
                                 const float* __restrict__ mod_age)
{
    __shared__ float a[LS];
    __shared__ int   ord[LS];
    __shared__ int   sid[LS];
    int b = blockIdx.x;
    int j = threadIdx.x;
    a[j] = mod_age[b * LS + j];
    __syncthreads();
    float aj = a[j];
    int r = 0;
    for (int i = 0; i < LS; i++) {
        float ai = a[i];
        r += (ai < aj) || (ai == aj && i < j);
    }
    ord[r] = j;
    __syncthreads();
    sid[j] = mod_idx[b * LS + ord[j]];
    __syncthreads();
    if (j == 0) {
        int c2 = 0, c3 = 0;
        for (int t = 0; t < LS; t++) {
            int s = sid[t];
            int src;
            if (s == 2) {
                int row = (c2 < HALF) ? c2 : (HALF - 1);
                c2++;
                src = b * HALF + row;
            } else {
                int row = (c3 < HALF) ? c3 : (HALF - 1);
                c3++;
                src = (b * HALF + row) | (1 << 30);
            }
            g_src[b * LS + t] = src;
        }
    }
}

// ----------------------------------------------------------------------------
// LayerNorm over 768-wide rows -> fp16 output. 256 threads, 3 elems each.
// ----------------------------------------------------------------------------
__device__ __forceinline__ void ln_row_body(const float* __restrict__ p,
                                            __half* __restrict__ o,
                                            const float* __restrict__ w,
                                            const float* __restrict__ bb)
{
    int t = threadIdx.x;
    float x0 = p[t], x1 = p[t + 256], x2 = p[t + 512];
    float s = x0 + x1 + x2;
    float q = x0 * x0 + x1 * x1 + x2 * x2;
    #pragma unroll
    for (int off = 16; off; off >>= 1) {
        s += __shfl_down_sync(FULLMASK, s, off);
        q += __shfl_down_sync(FULLMASK, q, off);
    }
    __shared__ float ss[8], sq[8];
    __shared__ float mr[2];
    int wid = t >> 5, lane = t & 31;
    if (lane == 0) { ss[wid] = s; sq[wid] = q; }
    __syncthreads();
    if (t == 0) {
        float S = 0.f, Q = 0.f;
        #pragma unroll
        for (int i = 0; i < 8; i++) { S += ss[i]; Q += sq[i]; }
        float mean = S * (1.f / NE);
        float var  = Q * (1.f / NE) - mean * mean;
        mr[0] = mean;
        mr[1] = rsqrtf(var + LN_EPS);
    }
    __syncthreads();
    float mean = mr[0], rstd = mr[1];
    o[t]       = __float2half_rn((x0 - mean) * rstd * w[t]       + bb[t]);
    o[t + 256] = __float2half_rn((x1 - mean) * rstd * w[t + 256] + bb[t + 256]);
    o[t + 512] = __float2half_rn((x2 - mean) * rstd * w[t + 512] + bb[t + 512]);
}

__global__ void ln_kernel(const float* __restrict__ in, __half* __restrict__ out,
                          const float* __restrict__ w, const float* __restrict__ b)
{
    int row = blockIdx.x;
    ln_row_body(in + (size_t)row * NE, out + (size_t)row * NE, w, b);
}

__global__ void fuse_ln_kernel(const float* __restrict__ mod2,
                               const float* __restrict__ mod3,
                               __half* __restrict__ out,
                               const float* __restrict__ w, const float* __restrict__ b)
{
    int row = blockIdx.x;
    int s = g_src[row];
    const float* tab = (s & (1 << 30)) ? mod3 : mod2;
    const float* p = tab + (size_t)(s & 0x3FFFFFFF) * NE;
    ln_row_body(p, out + (size_t)row * NE, w, b);
}

// ----------------------------------------------------------------------------
// HMMA fp16 GEMM: C[M,N] = A[M,K] @ W[N,K]^T + bias[N]  (+epilogue)
// 128x128x32 tile, 256 threads, warp tile 32x64, mma.m16n8k16.f16, cp.async
// double buffer, padded smem (stride 40 halves = conflict-free ldmatrix).
// EPI: 0 = fp32 out; 1 = fp32 out + residual; 2 = gelu -> fp16 out
// ----------------------------------------------------------------------------
#define BM 128
#define BN 128
#define BK 32
#define LDS_P 40   // padded row stride in half elems (80 bytes)

template<int EPI>
__global__ void __launch_bounds__(256, 2)
hgemm_kernel(const __half* __restrict__ A, const __half* __restrict__ W,
             const float* __restrict__ bias, const float* __restrict__ res,
             void* __restrict__ Cout, int M, int N, int K)
{
    __shared__ __half sA[2][BM * LDS_P];
    __shared__ __half sB[2][BN * LDS_P];

    const int tid = threadIdx.x;
    const int lane = tid & 31, wid = tid >> 5;
    const int warp_m = wid & 3, warp_n = wid >> 2;   // 4 x 2 warp grid
    const int m0 = blockIdx.y * BM, n0 = blockIdx.x * BN;

    float acc[2][8][4];
    #pragma unroll
    for (int im = 0; im < 2; im++)
        #pragma unroll
        for (int jn = 0; jn < 8; jn++)
            #pragma unroll
            for (int r = 0; r < 4; r++) acc[im][jn][r] = 0.f;

    const int a_row  = warp_m * 32 + (lane & 15);
    const int a_colh = (lane >> 4) << 3;
    const int b_row  = warp_n * 64 + (lane & 7) + ((lane >> 4) << 3);
    const int b_colh = ((lane >> 3) & 1) << 3;

    const int ld_row = tid >> 2;          // 0..63 (x2 halves)
    const int ld_sub = tid & 3;           // 16B chunk within 64B row

    const int nk = K / BK;

    auto load_stage = [&](int s, int kt) {
        const __half* Ag = A + (size_t)m0 * K + kt * BK;
        const __half* Bg = W + (size_t)n0 * K + kt * BK;
        #pragma unroll
        for (int i = 0; i < 2; i++) {
            int row = ld_row + i * 64;
            uint32_t da = smem_u32(&sA[s][row * LDS_P + ld_sub * 8]);
            const void* ga = Ag + (size_t)row * K + ld_sub * 8;
            asm volatile("cp.async.cg.shared.global [%0], [%1], 16;" :: "r"(da), "l"(ga));
            uint32_t db = smem_u32(&sB[s][row * LDS_P + ld_sub * 8]);
            const void* gb = Bg + (size_t)row * K + ld_sub * 8;
            asm volatile("cp.async.cg.shared.global [%0], [%1], 16;" :: "r"(db), "l"(gb));
        }
        asm volatile("cp.async.commit_group;" ::: "memory");
    };

    load_stage(0, 0);

    for (int kt = 0; kt < nk; kt++) {
        const int buf = kt & 1;
        if (kt + 1 < nk) {
            load_stage(buf ^ 1, kt + 1);
            asm volatile("cp.async.wait_group 1;" ::: "memory");
        } else {
            asm volatile("cp.async.wait_group 0;" ::: "memory");
        }
        __syncthreads();

        #pragma unroll
        for (int ks = 0; ks < 2; ks++) {
            uint32_t af[2][4];
            #pragma unroll
            for (int im = 0; im < 2; im++) {
                uint32_t addr = smem_u32(&sA[buf][(a_row + im * 16) * LDS_P + ks * 16 + a_colh]);
                asm volatile("ldmatrix.sync.aligned.m8n8.x4.shared.b16 {%0,%1,%2,%3}, [%4];"
                             : "=r"(af[im][0]), "=r"(af[im][1]), "=r"(af[im][2]), "=r"(af[im][3])
                             : "r"(addr));
            }
            uint32_t bf[8][2];
            #pragma unroll
            for (int j4 = 0; j4 < 4; j4++) {
                uint32_t r0, r1, r2, r3;
                uint32_t addr = smem_u32(&sB[buf][(b_row + j4 * 16) * LDS_P + ks * 16 + b_colh]);
                asm volatile("ldmatrix.sync.aligned.m8n8.x4.shared.b16 {%0,%1,%2,%3}, [%4];"
                             : "=r"(r0), "=r"(r1), "=r"(r2), "=r"(r3) : "r"(addr));
                bf[2 * j4][0] = r0; bf[2 * j4][1] = r1;
                bf[2 * j4 + 1][0] = r2; bf[2 * j4 + 1][1] = r3;
            }
            #pragma unroll
            for (int im = 0; im < 2; im++)
                #pragma unroll
                for (int jn = 0; jn < 8; jn++) {
                    asm volatile(
                        "mma.sync.aligned.m16n8k16.row.col.f32.f16.f16.f32 "
                        "{%0,%1,%2,%3}, {%4,%5,%6,%7}, {%8,%9}, {%0,%1,%2,%3};"
                        : "+f"(acc[im][jn][0]), "+f"(acc[im][jn][1]),
                          "+f"(acc[im][jn][2]), "+f"(acc[im][jn][3])
                        : "r"(af[im][0]), "r"(af[im][1]), "r"(af[im][2]), "r"(af[im][3]),
                          "r"(bf[jn][0]), "r"(bf[jn][1]));
                }
        }
        __syncthreads();
    }

    // --- epilogue ---
    #pragma unroll
    for (int im = 0; im < 2; im++) {
        #pragma unroll
        for (int jn = 0; jn < 8; jn++) {
            int n = n0 + warp_n * 64 + jn * 8 + (lane & 3) * 2;
            float b0 = bias[n], b1 = bias[n + 1];
            #pragma unroll
            for (int rp = 0; rp < 2; rp++) {
                int m = m0 + warp_m * 32 + im * 16 + (lane >> 2) + 8 * rp;
                float v0 = acc[im][jn][2 * rp]     + b0;
                float v1 = acc[im][jn][2 * rp + 1] + b1;
                if (EPI == 1) {
                    const float* rr = res + (size_t)m * N + n;
                    v0 += rr[0]; v1 += rr[1];
                }
                if (EPI == 2) {
                    v0 = 0.5f * v0 * (1.f + erff(v0 * 0.70710678118654752f));
                    v1 = 0.5f * v1 * (1.f + erff(v1 * 0.70710678118654752f));
                    *(__half2*)((__half*)Cout + (size_t)m * N + n) = __floats2half2_rn(v0, v1);
                } else {
                    *(float2*)((float*)Cout + (size_t)m * N + n) = make_float2(v0, v1);
                }
            }
        }
    }
}

// ----------------------------------------------------------------------------
// Attention: per (b,h), prefix-masked flash-style. Warp per q-row.
// q and p broadcast via smem. Output fp16.
// ----------------------------------------------------------------------------
__global__ void __launch_bounds__(256)
attn_kernel(const float* __restrict__ Q, const float* __restrict__ Kmat,
            const float* __restrict__ V, const float* __restrict__ age,
            const float* __restrict__ mage, __half* __restrict__ Y)
{
    int b = blockIdx.z, h = blockIdx.y;
    int qbase = blockIdx.x * 8;
    int tid = threadIdx.x, wid = tid >> 5, lane = tid & 31;
    int qrow = qbase + wid;

    __shared__ float KT[64][64];   // [d][key]
    __shared__ float Vs[64][64];   // [key][d]
    __shared__ float Qs[8][64];
    __shared__ float Ps[8][64];
    __shared__ int   s_kmax[8];

    float a = age[b * LM + qrow];
    int km = 0;
    if (lane == 0) {
        const float* ma = mage + b * LS;
        int lo = 0, hi = LS;
        while (lo < hi) {
            int mid = (lo + hi) >> 1;
            if (ma[mid] <= a) lo = mid + 1; else hi = mid;
        }
        km = lo;
        s_kmax[wid] = lo;
    }
    km = __shfl_sync(FULLMASK, km, 0);

    const float* qp = Q + (size_t)(b * LM + qrow) * NE + h * HD;
    Qs[wid][lane]      = qp[lane];
    Qs[wid][lane + 32] = qp[lane + 32];
    __syncthreads();
    int kmax_max = 0;
    #pragma unroll
    for (int i = 0; i < 8; i++) kmax_max = max(kmax_max, s_kmax[i]);

    float m = -INFINITY, l = 0.f, y0 = 0.f, y1 = 0.f;

    for (int kt = 0; kt < kmax_max; kt += 64) {
        {
            int key = tid >> 2;
            int dbase = (tid & 3) * 16;
            const float* kp = Kmat + (size_t)(b * LS + kt + key) * NE + h * HD + dbase;
            const float* vp = V    + (size_t)(b * LS + kt + key) * NE + h * HD + dbase;
            #pragma unroll
            for (int i = 0; i < 4; i++) {
                float4 kv = *(const float4*)(kp + i * 4);
                KT[dbase + i * 4 + 0][key] = kv.x;
                KT[dbase + i * 4 + 1][key] = kv.y;
                KT[dbase + i * 4 + 2][key] = kv.z;
                KT[dbase + i * 4 + 3][key] = kv.w;
                *(float4*)&Vs[key][dbase + i * 4] = *(const float4*)(vp + i * 4);
            }
        }
        __syncthreads();

        if (kt < km) {
            float s0 = 0.f, s1 = 0.f;
            #pragma unroll
            for (int d = 0; d < 64; d++) {
                float qd = Qs[wid][d];
                float2 kk = *(const float2*)&KT[d][2 * lane];
                s0 = fmaf(qd, kk.x, s0);
                s1 = fmaf(qd, kk.y, s1);
            }
            s0 *= 0.125f; s1 *= 0.125f;
            int kg = kt + 2 * lane;
            if (kg     >= km) s0 = -INFINITY;
            if (kg + 1 >= km) s1 = -INFINITY;

            float mt = fmaxf(s0, s1);
            #pragma unroll
            for (int o = 16; o; o >>= 1)
                mt = fmaxf(mt, __shfl_xor_sync(FULLMASK, mt, o));
            float mnew = fmaxf(m, mt);
            float corr = __expf(m - mnew);
            float p0 = __expf(s0 - mnew);
            float p1 = __expf(s1 - mnew);
            float ps = p0 + p1;
            #pragma unroll
            for (int o = 16; o; o >>= 1)
                ps += __shfl_xor_sync(FULLMASK, ps, o);
            l = l * corr + ps;
            y0 *= corr; y1 *= corr;
            m = mnew;

            Ps[wid][2 * lane]     = p0;
            Ps[wid][2 * lane + 1] = p1;
            __syncwarp();
            #pragma unroll
            for (int k2 = 0; k2 < 64; k2++) {
                float pk = Ps[wid][k2];
                float2 vv = *(const float2*)&Vs[k2][2 * lane];
                y0 = fmaf(pk, vv.x, y0);
                y1 = fmaf(pk, vv.y, y1);
            }
        }
        __syncthreads();
    }

    float inv = (l > 0.f) ? (1.f / l) : 0.f;
    __half* yp = Y + (size_t)(b * LM + qrow) * NE + h * HD;
    yp[2 * lane]     = __float2half_rn(y0 * inv);
    yp[2 * lane + 1] = __float2half_rn(y1 * inv);
}

// ----------------------------------------------------------------------------
// Launch  (ordered so ncu -s 5 captures the first hgemm)
// ----------------------------------------------------------------------------
extern "C" void kernel_launch(void* const* d_in, const int* in_sizes, int n_in,
                              void* d_out, int out_size)
{
    const float* x        = (const float*)d_in[0];
    const float* age      = (const float*)d_in[1];
    const int*   mod_idx  = (const int*)  d_in[2];
    const float* mod_age  = (const float*)d_in[3];
    const float* mod2     = (const float*)d_in[4];
    const float* mod3     = (const float*)d_in[5];
    const float* ln0_w    = (const float*)d_in[6];
    const float* ln0_b    = (const float*)d_in[7];
    const float* ln1_w    = (const float*)d_in[8];
    const float* ln1_b    = (const float*)d_in[9];
    const float* ln2_w    = (const float*)d_in[10];
    const float* ln2_b    = (const float*)d_in[11];
    const float* q_w      = (const float*)d_in[12];
    const float* q_b      = (const float*)d_in[13];
    const float* k_w      = (const float*)d_in[14];
    const float* k_b      = (const float*)d_in[15];
    const float* v_w      = (const float*)d_in[16];
    const float* v_b      = (const float*)d_in[17];
    const float* c_w      = (const float*)d_in[18];
    const float* c_b      = (const float*)d_in[19];
    const float* fc_w     = (const float*)d_in[20];
    const float* fc_b     = (const float*)d_in[21];
    const float* proj_w   = (const float*)d_in[22];
    const float* proj_b   = (const float*)d_in[23];
    float* out = (float*)d_out;

    float *p_q, *p_k, *p_v, *p_x1;
    __half *p_xnh, *p_snh, *p_yh, *p_hh;
    __half *p_wq, *p_wk, *p_wv, *p_wc, *p_wfc, *p_wpr;
    cudaGetSymbolAddress((void**)&p_q,   g_q);
    cudaGetSymbolAddress((void**)&p_k,   g_k);
    cudaGetSymbolAddress((void**)&p_v,   g_v);
    cudaGetSymbolAddress((void**)&p_x1,  g_x1);
    cudaGetSymbolAddress((void**)&p_xnh, g_xnh);
    cudaGetSymbolAddress((void**)&p_snh, g_snh);
    cudaGetSymbolAddress((void**)&p_yh,  g_yh);
    cudaGetSymbolAddress((void**)&p_hh,  g_hh);
    cudaGetSymbolAddress((void**)&p_wq,  g_wq);
    cudaGetSymbolAddress((void**)&p_wk,  g_wk);
    cudaGetSymbolAddress((void**)&p_wv,  g_wv);
    cudaGetSymbolAddress((void**)&p_wc,  g_wc);
    cudaGetSymbolAddress((void**)&p_wfc, g_wfc);
    cudaGetSymbolAddress((void**)&p_wpr, g_wpr);

    const int WSQ = NE * NE, WFC = FCD * NE;
    dim3 g768(NE / 128, NTOK / 128);
    dim3 gfc(FCD / 128, NTOK / 128);
    dim3 ga(LM / 8, NH, NB);

    // launches 0-4: prep, LN, first two weight converts
    fuse_prep_kernel<<<NB, LS>>>(mod_idx, mod_age);                    // 0
    ln_kernel<<<NTOK, 256>>>(x, p_xnh, ln1_w, ln1_b);                  // 1
    fuse_ln_kernel<<<NTOK, 256>>>(mod2, mod3, p_snh, ln0_w, ln0_b);    // 2
    f2h_kernel<<<WSQ / 512, 256>>>(q_w, p_wq, WSQ);                    // 3
    f2h_kernel<<<WSQ / 512, 256>>>(k_w, p_wk, WSQ);                    // 4

    // launch 5: first GEMM  <-- ncu -s 5 -c 1 captures this
    hgemm_kernel<0><<<g768, 256>>>(p_xnh, p_wq, q_b, nullptr, p_q, NTOK, NE, NE);   // 5

    f2h_kernel<<<WSQ / 512, 256>>>(v_w, p_wv, WSQ);                    // 6
    hgemm_kernel<0><<<g768, 256>>>(p_snh, p_wk, k_b, nullptr, p_k, NTOK, NE, NE);
    hgemm_kernel<0><<<g768, 256>>>(p_snh, p_wv, v_b, nullptr, p_v, NTOK, NE, NE);

    attn_kernel<<<ga, 256>>>(p_q, p_k, p_v, age, mod_age, p_yh);

    f2h_kernel<<<WSQ / 512, 256>>>(c_w, p_wc, WSQ);
    hgemm_kernel<1><<<g768, 256>>>(p_yh, p_wc, c_b, x, p_x1, NTOK, NE, NE);

    ln_kernel<<<NTOK, 256>>>(p_x1, p_xnh, ln2_w, ln2_b);
    f2h_kernel<<<WFC / 512, 256>>>(fc_w, p_wfc, WFC);
    hgemm_kernel<2><<<gfc, 256>>>(p_xnh, p_wfc, fc_b, nullptr, p_hh, NTOK, FCD, NE);
    f2h_kernel<<<WFC / 512, 256>>>(proj_w, p_wpr, WFC);
    hgemm_kernel<1><<<g768, 256>>>(p_hh, p_wpr, proj_b, p_x1, out, NTOK, NE, FCD);
}

// round 8
// speedup vs baseline: 2.4449x; 1.6902x over previous
#include <cuda_runtime.h>
#include <cuda_fp16.h>
#include <math.h>
#include <stdint.h>

// ----------------------------------------------------------------------------
// Problem constants
// ----------------------------------------------------------------------------
#define NB 4
#define LM 1024
#define LS 1024
#define NE 768
#define NH 12
#define HD 64
#define HALF 512
#define NTOK (NB * LM)          // 4096
#define FCD (4 * NE)            // 3072
#define LN_EPS 1e-5f
#define FULLMASK 0xffffffffu

// ----------------------------------------------------------------------------
// Scratch (device globals -- no runtime allocation allowed)
// ----------------------------------------------------------------------------
__device__ float g_q [NTOK * NE];
__device__ float g_k [NTOK * NE];
__device__ float g_v [NTOK * NE];
__device__ float g_x1[NTOK * NE];
__device__ __half g_xnh[NTOK * NE];   // LN outputs (fp16)
__device__ __half g_snh[NTOK * NE];
__device__ __half g_yh [NTOK * NE];   // attention out (fp16)
__device__ __half g_hh [NTOK * FCD]; // GELU activations (fp16)
__device__ __half g_wq [NE * NE];     // weights (fp16)
__device__ __half g_wk [NE * NE];
__device__ __half g_wv [NE * NE];
__device__ __half g_wc [NE * NE];
__device__ __half g_wfc[FCD * NE];
__device__ __half g_wpr[NE * FCD];
__device__ int g_src[NB * LS];

__device__ __forceinline__ uint32_t smem_u32(const void* p) {
    return (uint32_t)__cvta_generic_to_shared(p);
}

// ----------------------------------------------------------------------------
// fp32 -> fp16 conversion (n divisible by 512)
// ----------------------------------------------------------------------------
__global__ void f2h_kernel(const float* __restrict__ in, __half* __restrict__ out, int n) {
    int i = (blockIdx.x * 256 + threadIdx.x) * 2;
    if (i < n) {
        float2 v = *(const float2*)(in + i);
        *(__half2*)(out + i) = __floats2half2_rn(v.x, v.y);
    }
}

// ----------------------------------------------------------------------------
// Kernel: stable argsort of mod_age + scatter bookkeeping
// ----------------------------------------------------------------------------
__global__ void fuse_prep_kernel(const int* __restrict__ mod_idx,
                                 const float* __restrict__ mod_age)
{
    __shared__ float a[LS];
    __shared__ int   ord[LS];
    __shared__ int   sid[LS];
    int b = blockIdx.x;
    int j = threadIdx.x;
    a[j] = mod_age[b * LS + j];
    __syncthreads();
    float aj = a[j];
    int r = 0;
    for (int i = 0; i < LS; i++) {
        float ai = a[i];
        r += (ai < aj) || (ai == aj && i < j);
    }
    ord[r] = j;
    __syncthreads();
    sid[j] = mod_idx[b * LS + ord[j]];
    __syncthreads();
    if (j == 0) {
        int c2 = 0, c3 = 0;
        for (int t = 0; t < LS; t++) {
            int s = sid[t];
            int src;
            if (s == 2) {
                int row = (c2 < HALF) ? c2 : (HALF - 1);
                c2++;
                src = b * HALF + row;
            } else {
                int row = (c3 < HALF) ? c3 : (HALF - 1);
                c3++;
                src = (b * HALF + row) | (1 << 30);
            }
            g_src[b * LS + t] = src;
        }
    }
}

// ----------------------------------------------------------------------------
// LayerNorm over 768-wide rows -> fp16 output. 256 threads, 3 elems each.
// ----------------------------------------------------------------------------
__device__ __forceinline__ void ln_row_body(const float* __restrict__ p,
                                            __half* __restrict__ o,
                                            const float* __restrict__ w,
                                            const float* __restrict__ bb)
{
    int t = threadIdx.x;
    float x0 = p[t], x1 = p[t + 256], x2 = p[t + 512];
    float s = x0 + x1 + x2;
    float q = x0 * x0 + x1 * x1 + x2 * x2;
    #pragma unroll
    for (int off = 16; off; off >>= 1) {
        s += __shfl_down_sync(FULLMASK, s, off);
        q += __shfl_down_sync(FULLMASK, q, off);
    }
    __shared__ float ss[8], sq[8];
    __shared__ float mr[2];
    int wid = t >> 5, lane = t & 31;
    if (lane == 0) { ss[wid] = s; sq[wid] = q; }
    __syncthreads();
    if (t == 0) {
        float S = 0.f, Q = 0.f;
        #pragma unroll
        for (int i = 0; i < 8; i++) { S += ss[i]; Q += sq[i]; }
        float mean = S * (1.f / NE);
        float var  = Q * (1.f / NE) - mean * mean;
        mr[0] = mean;
        mr[1] = rsqrtf(var + LN_EPS);
    }
    __syncthreads();
    float mean = mr[0], rstd = mr[1];
    o[t]       = __float2half_rn((x0 - mean) * rstd * w[t]       + bb[t]);
    o[t + 256] = __float2half_rn((x1 - mean) * rstd * w[t + 256] + bb[t + 256]);
    o[t + 512] = __float2half_rn((x2 - mean) * rstd * w[t + 512] + bb[t + 512]);
}

__global__ void ln_kernel(const float* __restrict__ in, __half* __restrict__ out,
                          const float* __restrict__ w, const float* __restrict__ b)
{
    int row = blockIdx.x;
    ln_row_body(in + (size_t)row * NE, out + (size_t)row * NE, w, b);
}

__global__ void fuse_ln_kernel(const float* __restrict__ mod2,
                               const float* __restrict__ mod3,
                               __half* __restrict__ out,
                               const float* __restrict__ w, const float* __restrict__ b)
{
    int row = blockIdx.x;
    int s = g_src[row];
    const float* tab = (s & (1 << 30)) ? mod3 : mod2;
    const float* p = tab + (size_t)(s & 0x3FFFFFFF) * NE;
    ln_row_body(p, out + (size_t)row * NE, w, b);
}

// ----------------------------------------------------------------------------
// HMMA fp16 GEMM: C[M,N] = A[M,K] @ W[N,K]^T + bias[N]  (+epilogue)
// 128x128x32 tile, 256 threads, warp tile 32x64, mma.m16n8k16.f16.
// 3-stage cp.async pipeline, ONE __syncthreads per K-iter.
// XOR-swizzled smem (64B rows, chunk ^ ((row>>1)&3)) -- conflict-free for
// both cp.async stores and every ldmatrix phase; 48KB static smem total.
// EPI: 0 = fp32 out; 1 = fp32 out + residual; 2 = gelu -> fp16 out
// ----------------------------------------------------------------------------
#define BM 128
#define BN 128
#define BK 32

__device__ __forceinline__ int sw_off(int r, int c) {
    // byte offset of 16B chunk c (0..3) in row r (0..127), 64B rows
    return r * 64 + ((c ^ ((r >> 1) & 3)) << 4);
}

template<int EPI>
__global__ void __launch_bounds__(256, 2)
hgemm_kernel(const __half* __restrict__ A, const __half* __restrict__ W,
             const float* __restrict__ bias, const float* __restrict__ res,
             void* __restrict__ Cout, int M, int N, int K)
{
    __shared__ __align__(128) __half sA[3][BM * BK];
    __shared__ __align__(128) __half sB[3][BN * BK];

    const int tid = threadIdx.x;
    const int lane = tid & 31, wid = tid >> 5;
    const int warp_m = wid & 3, warp_n = wid >> 2;   // 4 x 2 warp grid
    const int m0 = blockIdx.y * BM, n0 = blockIdx.x * BN;

    float acc[2][8][4];
    #pragma unroll
    for (int im = 0; im < 2; im++)
        #pragma unroll
        for (int jn = 0; jn < 8; jn++)
            #pragma unroll
            for (int r = 0; r < 4; r++) acc[im][jn][r] = 0.f;

    const int ld_row = tid >> 2;          // 0..63 (x2 halves)
    const int ld_sub = tid & 3;           // 16B chunk within 64B row

    const int nk = K / BK;

    auto load_stage = [&](int s, int kt) {
        const __half* Ag = A + (size_t)m0 * K + kt * BK;
        const __half* Bg = W + (size_t)n0 * K + kt * BK;
        #pragma unroll
        for (int i = 0; i < 2; i++) {
            int row = ld_row + i * 64;
            int off = sw_off(row, ld_sub);
            uint32_t da = smem_u32((const uint8_t*)sA[s] + off);
            const void* ga = Ag + (size_t)row * K + ld_sub * 8;
            asm volatile("cp.async.cg.shared.global [%0], [%1], 16;" :: "r"(da), "l"(ga));
            uint32_t db = smem_u32((const uint8_t*)sB[s] + off);
            const void* gb = Bg + (size_t)row * K + ld_sub * 8;
            asm volatile("cp.async.cg.shared.global [%0], [%1], 16;" :: "r"(db), "l"(gb));
        }
    };

    load_stage(0, 0);
    asm volatile("cp.async.commit_group;" ::: "memory");
    load_stage(1, 1);
    asm volatile("cp.async.commit_group;" ::: "memory");

    // fragment row/chunk indices (within 128x32 tile)
    const int a_r0   = warp_m * 32 + (lane & 15);   // + im*16
    const int a_ch   = lane >> 4;                    // 0/1  -> + ks*2
    const int b_r0   = warp_n * 64 + (lane & 7) + ((lane >> 4) << 3);  // + j4*16
    const int b_ch   = (lane >> 3) & 1;              // 0/1  -> + ks*2

    int buf = 0;
    for (int kt = 0; kt < nk; kt++) {
        asm volatile("cp.async.wait_group 1;" ::: "memory");
        __syncthreads();
        if (kt + 2 < nk) {
            int s2 = buf + 2; if (s2 >= 3) s2 -= 3;
            load_stage(s2, kt + 2);
        }
        asm volatile("cp.async.commit_group;" ::: "memory");

        const uint32_t baseA = smem_u32(sA[buf]);
        const uint32_t baseB = smem_u32(sB[buf]);

        #pragma unroll
        for (int ks = 0; ks < 2; ks++) {
            uint32_t af[2][4];
            #pragma unroll
            for (int im = 0; im < 2; im++) {
                int r = a_r0 + im * 16;
                uint32_t addr = baseA + sw_off(r, ks * 2 + a_ch);
                asm volatile("ldmatrix.sync.aligned.m8n8.x4.shared.b16 {%0,%1,%2,%3}, [%4];"
                             : "=r"(af[im][0]), "=r"(af[im][1]), "=r"(af[im][2]), "=r"(af[im][3])
                             : "r"(addr));
            }
            uint32_t bf[8][2];
            #pragma unroll
            for (int j4 = 0; j4 < 4; j4++) {
                uint32_t r0, r1, r2, r3;
                int r = b_r0 + j4 * 16;
                uint32_t addr = baseB + sw_off(r, ks * 2 + b_ch);
                asm volatile("ldmatrix.sync.aligned.m8n8.x4.shared.b16 {%0,%1,%2,%3}, [%4];"
                             : "=r"(r0), "=r"(r1), "=r"(r2), "=r"(r3) : "r"(addr));
                bf[2 * j4][0] = r0; bf[2 * j4][1] = r1;
                bf[2 * j4 + 1][0] = r2; bf[2 * j4 + 1][1] = r3;
            }
            #pragma unroll
            for (int im = 0; im < 2; im++)
                #pragma unroll
                for (int jn = 0; jn < 8; jn++) {
                    asm volatile(
                        "mma.sync.aligned.m16n8k16.row.col.f32.f16.f16.f32 "
                        "{%0,%1,%2,%3}, {%4,%5,%6,%7}, {%8,%9}, {%0,%1,%2,%3};"
                        : "+f"(acc[im][jn][0]), "+f"(acc[im][jn][1]),
                          "+f"(acc[im][jn][2]), "+f"(acc[im][jn][3])
                        : "r"(af[im][0]), "r"(af[im][1]), "r"(af[im][2]), "r"(af[im][3]),
                          "r"(bf[jn][0]), "r"(bf[jn][1]));
                }
        }
        buf++; if (buf == 3) buf = 0;
    }

    // --- epilogue ---
    #pragma unroll
    for (int im = 0; im < 2; im++) {
        #pragma unroll
        for (int jn = 0; jn < 8; jn++) {
            int n = n0 + warp_n * 64 + jn * 8 + (lane & 3) * 2;
            float b0 = bias[n], b1 = bias[n + 1];
            #pragma unroll
            for (int rp = 0; rp < 2; rp++) {
                int m = m0 + warp_m * 32 + im * 16 + (lane >> 2) + 8 * rp;
                float v0 = acc[im][jn][2 * rp]     + b0;
                float v1 = acc[im][jn][2 * rp + 1] + b1;
                if (EPI == 1) {
                    const float* rr = res + (size_t)m * N + n;
                    v0 += rr[0]; v1 += rr[1];
                }
                if (EPI == 2) {
                    v0 = 0.5f * v0 * (1.f + erff(v0 * 0.70710678118654752f));
                    v1 = 0.5f * v1 * (1.f + erff(v1 * 0.70710678118654752f));
                    *(__half2*)((__half*)Cout + (size_t)m * N + n) = __floats2half2_rn(v0, v1);
                } else {
                    *(float2*)((float*)Cout + (size_t)m * N + n) = make_float2(v0, v1);
                }
            }
        }
    }
}

// ----------------------------------------------------------------------------
// Attention: per (b,h), prefix-masked flash-style. Warp per q-row.
// q and p broadcast via smem. Output fp16.
// ----------------------------------------------------------------------------
__global__ void __launch_bounds__(256)
attn_kernel(const float* __restrict__ Q, const float* __restrict__ Kmat,
            const float* __restrict__ V, const float* __restrict__ age,
            const float* __restrict__ mage, __half* __restrict__ Y)
{
    int b = blockIdx.z, h = blockIdx.y;
    int qbase = blockIdx.x * 8;
    int tid = threadIdx.x, wid = tid >> 5, lane = tid & 31;
    int qrow = qbase + wid;

    __shared__ float KT[64][64];   // [d][key]
    __shared__ float Vs[64][64];   // [key][d]
    __shared__ float Qs[8][64];
    __shared__ float Ps[8][64];
    __shared__ int   s_kmax[8];

    float a = age[b * LM + qrow];
    int km = 0;
    if (lane == 0) {
        const float* ma = mage + b * LS;
        int lo = 0, hi = LS;
        while (lo < hi) {
            int mid = (lo + hi) >> 1;
            if (ma[mid] <= a) lo = mid + 1; else hi = mid;
        }
        km = lo;
        s_kmax[wid] = lo;
    }
    km = __shfl_sync(FULLMASK, km, 0);

    const float* qp = Q + (size_t)(b * LM + qrow) * NE + h * HD;
    Qs[wid][lane]      = qp[lane];
    Qs[wid][lane + 32] = qp[lane + 32];
    __syncthreads();
    int kmax_max = 0;
    #pragma unroll
    for (int i = 0; i < 8; i++) kmax_max = max(kmax_max, s_kmax[i]);

    float m = -INFINITY, l = 0.f, y0 = 0.f, y1 = 0.f;

    for (int kt = 0; kt < kmax_max; kt += 64) {
        {
            int key = tid >> 2;
            int dbase = (tid & 3) * 16;
            const float* kp = Kmat + (size_t)(b * LS + kt + key) * NE + h * HD + dbase;
            const float* vp = V    + (size_t)(b * LS + kt + key) * NE + h * HD + dbase;
            #pragma unroll
            for (int i = 0; i < 4; i++) {
                float4 kv = *(const float4*)(kp + i * 4);
                KT[dbase + i * 4 + 0][key] = kv.x;
                KT[dbase + i * 4 + 1][key] = kv.y;
                KT[dbase + i * 4 + 2][key] = kv.z;
                KT[dbase + i * 4 + 3][key] = kv.w;
                *(float4*)&Vs[key][dbase + i * 4] = *(const float4*)(vp + i * 4);
            }
        }
        __syncthreads();

        if (kt < km) {
            float s0 = 0.f, s1 = 0.f;
            #pragma unroll
            for (int d = 0; d < 64; d++) {
                float qd = Qs[wid][d];
                float2 kk = *(const float2*)&KT[d][2 * lane];
                s0 = fmaf(qd, kk.x, s0);
                s1 = fmaf(qd, kk.y, s1);
            }
            s0 *= 0.125f; s1 *= 0.125f;
            int kg = kt + 2 * lane;
            if (kg     >= km) s0 = -INFINITY;
            if (kg + 1 >= km) s1 = -INFINITY;

            float mt = fmaxf(s0, s1);
            #pragma unroll
            for (int o = 16; o; o >>= 1)
                mt = fmaxf(mt, __shfl_xor_sync(FULLMASK, mt, o));
            float mnew = fmaxf(m, mt);
            float corr = __expf(m - mnew);
            float p0 = __expf(s0 - mnew);
            float p1 = __expf(s1 - mnew);
            float ps = p0 + p1;
            #pragma unroll
            for (int o = 16; o; o >>= 1)
                ps += __shfl_xor_sync(FULLMASK, ps, o);
            l = l * corr + ps;
            y0 *= corr; y1 *= corr;
            m = mnew;

            Ps[wid][2 * lane]     = p0;
            Ps[wid][2 * lane + 1] = p1;
            __syncwarp();
            #pragma unroll
            for (int k2 = 0; k2 < 64; k2++) {
                float pk = Ps[wid][k2];
                float2 vv = *(const float2*)&Vs[k2][2 * lane];
                y0 = fmaf(pk, vv.x, y0);
                y1 = fmaf(pk, vv.y, y1);
            }
        }
        __syncthreads();
    }

    float inv = (l > 0.f) ? (1.f / l) : 0.f;
    __half* yp = Y + (size_t)(b * LM + qrow) * NE + h * HD;
    yp[2 * lane]     = __float2half_rn(y0 * inv);
    yp[2 * lane + 1] = __float2half_rn(y1 * inv);
}

// ----------------------------------------------------------------------------
// Launch  (my index 4 = first hgemm; harness injects one launch ahead,
//          so ncu's "-s 5 -c 1" should land on it)
// ----------------------------------------------------------------------------
extern "C" void kernel_launch(void* const* d_in, const int* in_sizes, int n_in,
                              void* d_out, int out_size)
{
    const float* x        = (const float*)d_in[0];
    const float* age      = (const float*)d_in[1];
    const int*   mod_idx  = (const int*)  d_in[2];
    const float* mod_age  = (const float*)d_in[3];
    const float* mod2     = (const float*)d_in[4];
    const float* mod3     = (const float*)d_in[5];
    const float* ln0_w    = (const float*)d_in[6];
    const float* ln0_b    = (const float*)d_in[7];
    const float* ln1_w    = (const float*)d_in[8];
    const float* ln1_b    = (const float*)d_in[9];
    const float* ln2_w    = (const float*)d_in[10];
    const float* ln2_b    = (const float*)d_in[11];
    const float* q_w      = (const float*)d_in[12];
    const float* q_b      = (const float*)d_in[13];
    const float* k_w      = (const float*)d_in[14];
    const float* k_b      = (const float*)d_in[15];
    const float* v_w      = (const float*)d_in[16];
    const float* v_b      = (const float*)d_in[17];
    const float* c_w      = (const float*)d_in[18];
    const float* c_b      = (const float*)d_in[19];
    const float* fc_w     = (const float*)d_in[20];
    const float* fc_b     = (const float*)d_in[21];
    const float* proj_w   = (const float*)d_in[22];
    const float* proj_b   = (const float*)d_in[23];
    float* out = (float*)d_out;

    float *p_q, *p_k, *p_v, *p_x1;
    __half *p_xnh, *p_snh, *p_yh, *p_hh;
    __half *p_wq, *p_wk, *p_wv, *p_wc, *p_wfc, *p_wpr;
    cudaGetSymbolAddress((void**)&p_q,   g_q);
    cudaGetSymbolAddress((void**)&p_k,   g_k);
    cudaGetSymbolAddress((void**)&p_v,   g_v);
    cudaGetSymbolAddress((void**)&p_x1,  g_x1);
    cudaGetSymbolAddress((void**)&p_xnh, g_xnh);
    cudaGetSymbolAddress((void**)&p_snh, g_snh);
    cudaGetSymbolAddress((void**)&p_yh,  g_yh);
    cudaGetSymbolAddress((void**)&p_hh,  g_hh);
    cudaGetSymbolAddress((void**)&p_wq,  g_wq);
    cudaGetSymbolAddress((void**)&p_wk,  g_wk);
    cudaGetSymbolAddress((void**)&p_wv,  g_wv);
    cudaGetSymbolAddress((void**)&p_wc,  g_wc);
    cudaGetSymbolAddress((void**)&p_wfc, g_wfc);
    cudaGetSymbolAddress((void**)&p_wpr, g_wpr);

    const int WSQ = NE * NE, WFC = FCD * NE;
    dim3 g768(NE / 128, NTOK / 128);
    dim3 gfc(FCD / 128, NTOK / 128);
    dim3 ga(LM / 8, NH, NB);

    fuse_prep_kernel<<<NB, LS>>>(mod_idx, mod_age);                    // 0
    ln_kernel<<<NTOK, 256>>>(x, p_xnh, ln1_w, ln1_b);                  // 1
    fuse_ln_kernel<<<NTOK, 256>>>(mod2, mod3, p_snh, ln0_w, ln0_b);    // 2
    f2h_kernel<<<WSQ / 512, 256>>>(q_w, p_wq, WSQ);                    // 3

    // my index 4: first GEMM  <-- intended ncu capture target
    hgemm_kernel<0><<<g768, 256>>>(p_xnh, p_wq, q_b, nullptr, p_q, NTOK, NE, NE);  // 4

    f2h_kernel<<<WSQ / 512, 256>>>(k_w, p_wk, WSQ);                    // 5
    f2h_kernel<<<WSQ / 512, 256>>>(v_w, p_wv, WSQ);                    // 6
    hgemm_kernel<0><<<g768, 256>>>(p_snh, p_wk, k_b, nullptr, p_k, NTOK, NE, NE);
    hgemm_kernel<0><<<g768, 256>>>(p_snh, p_wv, v_b, nullptr, p_v, NTOK, NE, NE);

    attn_kernel<<<ga, 256>>>(p_q, p_k, p_v, age, mod_age, p_yh);

    f2h_kernel<<<WSQ / 512, 256>>>(c_w, p_wc, WSQ);
    hgemm_kernel<1><<<g768, 256>>>(p_yh, p_wc, c_b, x, p_x1, NTOK, NE, NE);

    ln_kernel<<<NTOK, 256>>>(p_x1, p_xnh, ln2_w, ln2_b);
    f2h_kernel<<<WFC / 512, 256>>>(fc_w, p_wfc, WFC);
    hgemm_kernel<2><<<gfc, 256>>>(p_xnh, p_wfc, fc_b, nullptr, p_hh, NTOK, FCD, NE);
    f2h_kernel<<<WFC / 512, 256>>>(proj_w, p_wpr, WFC);
    hgemm_kernel<1><<<g768, 256>>>(p_hh, p_wpr, proj_b, p_x1, out, NTOK, NE, FCD);
}

// round 10
// speedup vs baseline: 8.1279x; 3.3245x over previous
#include <cuda_runtime.h>
#include <cuda_fp16.h>
#include <math.h>
#include <stdint.h>

// ----------------------------------------------------------------------------
// Problem constants
// ----------------------------------------------------------------------------
#define NB 4
#define LM 1024
#define LS 1024
#define NE 768
#define NH 12
#define HD 64
#define HALF 512
#define NTOK (NB * LM)          // 4096
#define FCD (4 * NE)            // 3072
#define LN_EPS 1e-5f
#define FULLMASK 0xffffffffu

// ----------------------------------------------------------------------------
// Scratch (device globals -- no runtime allocation allowed)
// ----------------------------------------------------------------------------
__device__ float  g_x1[NTOK * NE];
__device__ __half g_qh [NTOK * NE];   // Q/K/V in fp16
__device__ __half g_kh [NTOK * NE];
__device__ __half g_vh [NTOK * NE];
__device__ __half g_xnh[NTOK * NE];   // LN outputs (fp16)
__device__ __half g_snh[NTOK * NE];
__device__ __half g_yh [NTOK * NE];   // attention out (fp16)
__device__ __half g_hh [NTOK * FCD]; // GELU activations (fp16)
__device__ __half g_wq [NE * NE];     // weights (fp16)
__device__ __half g_wk [NE * NE];
__device__ __half g_wv [NE * NE];
__device__ __half g_wc [NE * NE];
__device__ __half g_wfc[FCD * NE];
__device__ __half g_wpr[NE * FCD];
__device__ int g_src[NB * LS];

__device__ __forceinline__ uint32_t smem_u32(const void* p) {
    return (uint32_t)__cvta_generic_to_shared(p);
}

// ----------------------------------------------------------------------------
// fp32 -> fp16 conversion (n divisible by 512)
// ----------------------------------------------------------------------------
__global__ void f2h_kernel(const float* __restrict__ in, __half* __restrict__ out, int n) {
    int i = (blockIdx.x * 256 + threadIdx.x) * 2;
    if (i < n) {
        float2 v = *(const float2*)(in + i);
        *(__half2*)(out + i) = __floats2half2_rn(v.x, v.y);
    }
}

// ----------------------------------------------------------------------------
// Kernel: stable argsort of mod_age + scatter bookkeeping
// ----------------------------------------------------------------------------
__global__ void fuse_prep_kernel(const int* __restrict__ mod_idx,
                                 const float* __restrict__ mod_age)
{
    __shared__ float a[LS];
    __shared__ int   ord[LS];
    __shared__ int   sid[LS];
    int b = blockIdx.x;
    int j = threadIdx.x;
    a[j] = mod_age[b * LS + j];
    __syncthreads();
    float aj = a[j];
    int r = 0;
    for (int i = 0; i < LS; i++) {
        float ai = a[i];
        r += (ai < aj) || (ai == aj && i < j);
    }
    ord[r] = j;
    __syncthreads();
    sid[j] = mod_idx[b * LS + ord[j]];
    __syncthreads();
    if (j == 0) {
        int c2 = 0, c3 = 0;
        for (int t = 0; t < LS; t++) {
            int s = sid[t];
            int src;
            if (s == 2) {
                int row = (c2 < HALF) ? c2 : (HALF - 1);
                c2++;
                src = b * HALF + row;
            } else {
                int row = (c3 < HALF) ? c3 : (HALF - 1);
                c3++;
                src = (b * HALF + row) | (1 << 30);
            }
            g_src[b * LS + t] = src;
        }
    }
}

// ----------------------------------------------------------------------------
// LayerNorm over 768-wide rows -> fp16 output. 256 threads, 3 elems each.
// ----------------------------------------------------------------------------
__device__ __forceinline__ void ln_row_body(const float* __restrict__ p,
                                            __half* __restrict__ o,
                                            const float* __restrict__ w,
                                            const float* __restrict__ bb)
{
    int t = threadIdx.x;
    float x0 = p[t], x1 = p[t + 256], x2 = p[t + 512];
    float s = x0 + x1 + x2;
    float q = x0 * x0 + x1 * x1 + x2 * x2;
    #pragma unroll
    for (int off = 16; off; off >>= 1) {
        s += __shfl_down_sync(FULLMASK, s, off);
        q += __shfl_down_sync(FULLMASK, q, off);
    }
    __shared__ float ss[8], sq[8];
    __shared__ float mr[2];
    int wid = t >> 5, lane = t & 31;
    if (lane == 0) { ss[wid] = s; sq[wid] = q; }
    __syncthreads();
    if (t == 0) {
        float S = 0.f, Q = 0.f;
        #pragma unroll
        for (int i = 0; i < 8; i++) { S += ss[i]; Q += sq[i]; }
        float mean = S * (1.f / NE);
        float var  = Q * (1.f / NE) - mean * mean;
        mr[0] = mean;
        mr[1] = rsqrtf(var + LN_EPS);
    }
    __syncthreads();
    float mean = mr[0], rstd = mr[1];
    o[t]       = __float2half_rn((x0 - mean) * rstd * w[t]       + bb[t]);
    o[t + 256] = __float2half_rn((x1 - mean) * rstd * w[t + 256] + bb[t + 256]);
    o[t + 512] = __float2half_rn((x2 - mean) * rstd * w[t + 512] + bb[t + 512]);
}

__global__ void ln_kernel(const float* __restrict__ in, __half* __restrict__ out,
                          const float* __restrict__ w, const float* __restrict__ b)
{
    int row = blockIdx.x;
    ln_row_body(in + (size_t)row * NE, out + (size_t)row * NE, w, b);
}

__global__ void fuse_ln_kernel(const float* __restrict__ mod2,
                               const float* __restrict__ mod3,
                               __half* __restrict__ out,
                               const float* __restrict__ w, const float* __restrict__ b)
{
    int row = blockIdx.x;
    int s = g_src[row];
    const float* tab = (s & (1 << 30)) ? mod3 : mod2;
    const float* p = tab + (size_t)(s & 0x3FFFFFFF) * NE;
    ln_row_body(p, out + (size_t)row * NE, w, b);
}

// ----------------------------------------------------------------------------
// HMMA fp16 GEMM (R8 structure): 128x128x32, 3-stage cp.async, 1 barrier/iter.
// EPI: 0 = fp32 out; 1 = fp32 out + residual; 2 = gelu -> fp16; 3 = fp16 out
// ----------------------------------------------------------------------------
#define BM 128
#define BN 128
#define BK 32

__device__ __forceinline__ int sw_off(int r, int c) {
    return r * 64 + ((c ^ ((r >> 1) & 3)) << 4);
}

template<int EPI>
__global__ void __launch_bounds__(256, 2)
hgemm_kernel(const __half* __restrict__ A, const __half* __restrict__ W,
             const float* __restrict__ bias, const float* __restrict__ res,
             void* __restrict__ Cout, int M, int N, int K)
{
    __shared__ __align__(128) __half sA[3][BM * BK];
    __shared__ __align__(128) __half sB[3][BN * BK];

    const int tid = threadIdx.x;
    const int lane = tid & 31, wid = tid >> 5;
    const int warp_m = wid & 3, warp_n = wid >> 2;
    const int m0 = blockIdx.y * BM, n0 = blockIdx.x * BN;

    float acc[2][8][4];
    #pragma unroll
    for (int im = 0; im < 2; im++)
        #pragma unroll
        for (int jn = 0; jn < 8; jn++)
            #pragma unroll
            for (int r = 0; r < 4; r++) acc[im][jn][r] = 0.f;

    const int ld_row = tid >> 2;
    const int ld_sub = tid & 3;
    const int nk = K / BK;

    auto load_stage = [&](int s, int kt) {
        const __half* Ag = A + (size_t)m0 * K + kt * BK;
        const __half* Bg = W + (size_t)n0 * K + kt * BK;
        #pragma unroll
        for (int i = 0; i < 2; i++) {
            int row = ld_row + i * 64;
            int off = sw_off(row, ld_sub);
            uint32_t da = smem_u32((const uint8_t*)sA[s] + off);
            const void* ga = Ag + (size_t)row * K + ld_sub * 8;
            asm volatile("cp.async.cg.shared.global [%0], [%1], 16;" :: "r"(da), "l"(ga));
            uint32_t db = smem_u32((const uint8_t*)sB[s] + off);
            const void* gb = Bg + (size_t)row * K + ld_sub * 8;
            asm volatile("cp.async.cg.shared.global [%0], [%1], 16;" :: "r"(db), "l"(gb));
        }
    };

    load_stage(0, 0);
    asm volatile("cp.async.commit_group;" ::: "memory");
    load_stage(1, 1);
    asm volatile("cp.async.commit_group;" ::: "memory");

    const int a_r0 = warp_m * 32 + (lane & 15);
    const int a_ch = lane >> 4;
    const int b_r0 = warp_n * 64 + (lane & 7) + ((lane >> 4) << 3);
    const int b_ch = (lane >> 3) & 1;

    int buf = 0;
    for (int kt = 0; kt < nk; kt++) {
        asm volatile("cp.async.wait_group 1;" ::: "memory");
        __syncthreads();
        if (kt + 2 < nk) {
            int s2 = buf + 2; if (s2 >= 3) s2 -= 3;
            load_stage(s2, kt + 2);
        }
        asm volatile("cp.async.commit_group;" ::: "memory");

        const uint32_t baseA = smem_u32(sA[buf]);
        const uint32_t baseB = smem_u32(sB[buf]);

        #pragma unroll
        for (int ks = 0; ks < 2; ks++) {
            uint32_t af[2][4];
            #pragma unroll
            for (int im = 0; im < 2; im++) {
                int r = a_r0 + im * 16;
                uint32_t addr = baseA + sw_off(r, ks * 2 + a_ch);
                asm volatile("ldmatrix.sync.aligned.m8n8.x4.shared.b16 {%0,%1,%2,%3}, [%4];"
                             : "=r"(af[im][0]), "=r"(af[im][1]), "=r"(af[im][2]), "=r"(af[im][3])
                             : "r"(addr));
            }
            uint32_t bf[8][2];
            #pragma unroll
            for (int j4 = 0; j4 < 4; j4++) {
                uint32_t r0, r1, r2, r3;
                int r = b_r0 + j4 * 16;
                uint32_t addr = baseB + sw_off(r, ks * 2 + b_ch);
                asm volatile("ldmatrix.sync.aligned.m8n8.x4.shared.b16 {%0,%1,%2,%3}, [%4];"
                             : "=r"(r0), "=r"(r1), "=r"(r2), "=r"(r3) : "r"(addr));
                bf[2 * j4][0] = r0; bf[2 * j4][1] = r1;
                bf[2 * j4 + 1][0] = r2; bf[2 * j4 + 1][1] = r3;
            }
            #pragma unroll
            for (int im = 0; im < 2; im++)
                #pragma unroll
                for (int jn = 0; jn < 8; jn++) {
                    asm volatile(
                        "mma.sync.aligned.m16n8k16.row.col.f32.f16.f16.f32 "
                        "{%0,%1,%2,%3}, {%4,%5,%6,%7}, {%8,%9}, {%0,%1,%2,%3};"
                        : "+f"(acc[im][jn][0]), "+f"(acc[im][jn][1]),
                          "+f"(acc[im][jn][2]), "+f"(acc[im][jn][3])
                        : "r"(af[im][0]), "r"(af[im][1]), "r"(af[im][2]), "r"(af[im][3]),
                          "r"(bf[jn][0]), "r"(bf[jn][1]));
                }
        }
        buf++; if (buf == 3) buf = 0;
    }

    #pragma unroll
    for (int im = 0; im < 2; im++) {
        #pragma unroll
        for (int jn = 0; jn < 8; jn++) {
            int n = n0 + warp_n * 64 + jn * 8 + (lane & 3) * 2;
            float b0 = bias[n], b1 = bias[n + 1];
            #pragma unroll
            for (int rp = 0; rp < 2; rp++) {
                int m = m0 + warp_m * 32 + im * 16 + (lane >> 2) + 8 * rp;
                float v0 = acc[im][jn][2 * rp]     + b0;
                float v1 = acc[im][jn][2 * rp + 1] + b1;
                if (EPI == 1) {
                    const float* rr = res + (size_t)m * N + n;
                    v0 += rr[0]; v1 += rr[1];
                }
                if (EPI == 2) {
                    v0 = 0.5f * v0 * (1.f + erff(v0 * 0.70710678118654752f));
                    v1 = 0.5f * v1 * (1.f + erff(v1 * 0.70710678118654752f));
                }
                if (EPI == 2 || EPI == 3) {
                    *(__half2*)((__half*)Cout + (size_t)m * N + n) = __floats2half2_rn(v0, v1);
                } else {
                    *(float2*)((float*)Cout + (size_t)m * N + n) = make_float2(v0, v1);
                }
            }
        }
    }
}

// ----------------------------------------------------------------------------
// Tensorized flash attention. CTA = 64 q-rows, 4 warps (16 rows each).
// 64-key tiles, fp16 mma, fp32 online softmax. Prefix mask via per-row km
// (monotonic: age and mod_age sorted). 128B-row swizzle: chunk ^ (row&7).
// ----------------------------------------------------------------------------
__device__ __forceinline__ int swb(int r, int c) {
    return r * 128 + ((c ^ (r & 7)) << 4);
}

__global__ void __launch_bounds__(128)
attn_mma_kernel(const __half* __restrict__ Q, const __half* __restrict__ K,
                const __half* __restrict__ V, const float* __restrict__ age,
                const float* __restrict__ mage, __half* __restrict__ Y)
{
    const int b = blockIdx.z, h = blockIdx.y;
    const int q0 = blockIdx.x * 64;
    const int tid = threadIdx.x, wid = tid >> 5, lane = tid & 31;

    __shared__ __align__(128) __half sQ[64 * 64];
    __shared__ __align__(128) __half sK[2][64 * 64];
    __shared__ __align__(128) __half sV[2][64 * 64];
    __shared__ int s_km[64];

    // Q tile (64 rows x 128B)
    #pragma unroll
    for (int i = 0; i < 4; i++) {
        int id = i * 128 + tid, r = id >> 3, c = id & 7;
        uint32_t d = smem_u32((uint8_t*)sQ + swb(r, c));
        const void* g = Q + ((size_t)(b * LM + q0 + r) * NE + h * HD + c * 8);
        asm volatile("cp.async.cg.shared.global [%0], [%1], 16;" :: "r"(d), "l"(g));
    }
    asm volatile("cp.async.commit_group;" ::: "memory");

    auto load_kv = [&](int s, int kt) {
        #pragma unroll
        for (int i = 0; i < 4; i++) {
            int id = i * 128 + tid, r = id >> 3, c = id & 7;
            size_t gofs = (size_t)(b * LS + kt + r) * NE + h * HD + c * 8;
            uint32_t dk = smem_u32((uint8_t*)sK[s] + swb(r, c));
            asm volatile("cp.async.cg.shared.global [%0], [%1], 16;" :: "r"(dk), "l"((const void*)(K + gofs)));
            uint32_t dv = smem_u32((uint8_t*)sV[s] + swb(r, c));
            asm volatile("cp.async.cg.shared.global [%0], [%1], 16;" :: "r"(dv), "l"((const void*)(V + gofs)));
        }
        asm volatile("cp.async.commit_group;" ::: "memory");
    };
    load_kv(0, 0);

    // per-row valid-key counts (sorted -> monotonic)
    if (tid < 64) {
        float a = age[b * LM + q0 + tid];
        const float* ma = mage + b * LS;
        int lo = 0, hi = LS;
        while (lo < hi) {
            int mid = (lo + hi) >> 1;
            if (ma[mid] <= a) lo = mid + 1; else hi = mid;
        }
        s_km[tid] = lo;
    }
    __syncthreads();

    const int rq    = lane >> 2;                 // 0..7
    const int km1   = s_km[wid * 16 + rq];
    const int km2   = s_km[wid * 16 + rq + 8];
    const int km_hi = s_km[wid * 16 + 15];
    const int nt    = (s_km[63] + 63) >> 6;

    float m1 = -INFINITY, m2 = -INFINITY, l1 = 0.f, l2 = 0.f;
    float o[8][4];
    #pragma unroll
    for (int j = 0; j < 8; j++)
        #pragma unroll
        for (int r = 0; r < 4; r++) o[j][r] = 0.f;
    uint32_t qf[4][4];

    for (int t = 0; t < nt; t++) {
        const int kt = t * 64;
        asm volatile("cp.async.wait_group 0;" ::: "memory");
        __syncthreads();
        if (t + 1 < nt) load_kv((t + 1) & 1, kt + 64);

        if (t == 0) {
            int ar = wid * 16 + (lane & 15);
            #pragma unroll
            for (int kc = 0; kc < 4; kc++) {
                uint32_t addr = smem_u32((uint8_t*)sQ + swb(ar, kc * 2 + (lane >> 4)));
                asm volatile("ldmatrix.sync.aligned.m8n8.x4.shared.b16 {%0,%1,%2,%3}, [%4];"
                             : "=r"(qf[kc][0]), "=r"(qf[kc][1]), "=r"(qf[kc][2]), "=r"(qf[kc][3])
                             : "r"(addr));
            }
        }

        if (kt < km_hi) {
            const int bufi = t & 1;
            float s[8][4];
            #pragma unroll
            for (int j = 0; j < 8; j++)
                #pragma unroll
                for (int r = 0; r < 4; r++) s[j][r] = 0.f;

            // S = Q @ K^T
            const int br = (lane & 7) + ((lane >> 4) << 3);
            const int bc = (lane >> 3) & 1;
            #pragma unroll
            for (int kc = 0; kc < 4; kc++) {
                uint32_t kf[8][2];
                #pragma unroll
                for (int j4 = 0; j4 < 4; j4++) {
                    uint32_t r0, r1, r2, r3;
                    int r = br + j4 * 16;
                    uint32_t addr = smem_u32((uint8_t*)sK[bufi] + swb(r, kc * 2 + bc));
                    asm volatile("ldmatrix.sync.aligned.m8n8.x4.shared.b16 {%0,%1,%2,%3}, [%4];"
                                 : "=r"(r0), "=r"(r1), "=r"(r2), "=r"(r3) : "r"(addr));
                    kf[2 * j4][0] = r0; kf[2 * j4][1] = r1;
                    kf[2 * j4 + 1][0] = r2; kf[2 * j4 + 1][1] = r3;
                }
                #pragma unroll
                for (int j = 0; j < 8; j++) {
                    asm volatile(
                        "mma.sync.aligned.m16n8k16.row.col.f32.f16.f16.f32 "
                        "{%0,%1,%2,%3}, {%4,%5,%6,%7}, {%8,%9}, {%0,%1,%2,%3};"
                        : "+f"(s[j][0]), "+f"(s[j][1]), "+f"(s[j][2]), "+f"(s[j][3])
                        : "r"(qf[kc][0]), "r"(qf[kc][1]), "r"(qf[kc][2]), "r"(qf[kc][3]),
                          "r"(kf[j][0]), "r"(kf[j][1]));
                }
            }

            // scale + prefix mask
            const int colb = kt + 2 * (lane & 3);
            #pragma unroll
            for (int j = 0; j < 8; j++) {
                int c0 = colb + 8 * j;
                s[j][0] = (c0     < km1) ? s[j][0] * 0.125f : -INFINITY;
                s[j][1] = (c0 + 1 < km1) ? s[j][1] * 0.125f : -INFINITY;
                s[j][2] = (c0     < km2) ? s[j][2] * 0.125f : -INFINITY;
                s[j][3] = (c0 + 1 < km2) ? s[j][3] * 0.125f : -INFINITY;
            }

            // online softmax (rows rq and rq+8)
            float mt1 = -INFINITY, mt2 = -INFINITY;
            #pragma unroll
            for (int j = 0; j < 8; j++) {
                mt1 = fmaxf(mt1, fmaxf(s[j][0], s[j][1]));
                mt2 = fmaxf(mt2, fmaxf(s[j][2], s[j][3]));
            }
            mt1 = fmaxf(mt1, __shfl_xor_sync(FULLMASK, mt1, 1));
            mt1 = fmaxf(mt1, __shfl_xor_sync(FULLMASK, mt1, 2));
            mt2 = fmaxf(mt2, __shfl_xor_sync(FULLMASK, mt2, 1));
            mt2 = fmaxf(mt2, __shfl_xor_sync(FULLMASK, mt2, 2));
            float mn1 = fmaxf(m1, mt1), mn2 = fmaxf(m2, mt2);
            float ms1 = fmaxf(mn1, -1e30f), ms2 = fmaxf(mn2, -1e30f);
            float corr1 = __expf(m1 - ms1), corr2 = __expf(m2 - ms2);
            float ps1 = 0.f, ps2 = 0.f;
            #pragma unroll
            for (int j = 0; j < 8; j++) {
                s[j][0] = __expf(s[j][0] - ms1);
                s[j][1] = __expf(s[j][1] - ms1);
                s[j][2] = __expf(s[j][2] - ms2);
                s[j][3] = __expf(s[j][3] - ms2);
                ps1 += s[j][0] + s[j][1];
                ps2 += s[j][2] + s[j][3];
            }
            ps1 += __shfl_xor_sync(FULLMASK, ps1, 1);
            ps1 += __shfl_xor_sync(FULLMASK, ps1, 2);
            ps2 += __shfl_xor_sync(FULLMASK, ps2, 1);
            ps2 += __shfl_xor_sync(FULLMASK, ps2, 2);
            l1 = l1 * corr1 + ps1;
            l2 = l2 * corr2 + ps2;
            m1 = mn1; m2 = mn2;
            #pragma unroll
            for (int j = 0; j < 8; j++) {
                o[j][0] *= corr1; o[j][1] *= corr1;
                o[j][2] *= corr2; o[j][3] *= corr2;
            }

            // O += P @ V   (P from S-frags; V via ldmatrix.trans)
            const int vr0 = ((lane >> 3) & 1) * 8 + (lane & 7);
            #pragma unroll
            for (int kc = 0; kc < 4; kc++) {
                uint32_t pa[4];
                __half2* pah = (__half2*)pa;
                pah[0] = __floats2half2_rn(s[2 * kc][0], s[2 * kc][1]);
                pah[1] = __floats2half2_rn(s[2 * kc][2], s[2 * kc][3]);
                pah[2] = __floats2half2_rn(s[2 * kc + 1][0], s[2 * kc + 1][1]);
                pah[3] = __floats2half2_rn(s[2 * kc + 1][2], s[2 * kc + 1][3]);
                #pragma unroll
                for (int dg = 0; dg < 4; dg++) {
                    uint32_t v0, v1, v2, v3;
                    int r = kc * 16 + vr0;
                    uint32_t addr = smem_u32((uint8_t*)sV[bufi] + swb(r, dg * 2 + (lane >> 4)));
                    asm volatile("ldmatrix.sync.aligned.m8n8.x4.trans.shared.b16 {%0,%1,%2,%3}, [%4];"
                                 : "=r"(v0), "=r"(v1), "=r"(v2), "=r"(v3) : "r"(addr));
                    asm volatile(
                        "mma.sync.aligned.m16n8k16.row.col.f32.f16.f16.f32 "
                        "{%0,%1,%2,%3}, {%4,%5,%6,%7}, {%8,%9}, {%0,%1,%2,%3};"
                        : "+f"(o[2 * dg][0]), "+f"(o[2 * dg][1]), "+f"(o[2 * dg][2]), "+f"(o[2 * dg][3])
                        : "r"(pa[0]), "r"(pa[1]), "r"(pa[2]), "r"(pa[3]), "r"(v0), "r"(v1));
                    asm volatile(
                        "mma.sync.aligned.m16n8k16.row.col.f32.f16.f16.f32 "
                        "{%0,%1,%2,%3}, {%4,%5,%6,%7}, {%8,%9}, {%0,%1,%2,%3};"
                        : "+f"(o[2 * dg + 1][0]), "+f"(o[2 * dg + 1][1]), "+f"(o[2 * dg + 1][2]), "+f"(o[2 * dg + 1][3])
                        : "r"(pa[0]), "r"(pa[1]), "r"(pa[2]), "r"(pa[3]), "r"(v2), "r"(v3));
                }
            }
        }
    }

    // normalize + store
    float inv1 = (l1 > 0.f) ? (1.f / l1) : 0.f;
    float inv2 = (l2 > 0.f) ? (1.f / l2) : 0.f;
    size_t row1 = (size_t)(b * LM + q0 + wid * 16 + rq);
    #pragma unroll
    for (int j = 0; j < 8; j++) {
        int col = h * HD + 8 * j + 2 * (lane & 3);
        *(__half2*)(Y + row1 * NE + col)       = __floats2half2_rn(o[j][0] * inv1, o[j][1] * inv1);
        *(__half2*)(Y + (row1 + 8) * NE + col) = __floats2half2_rn(o[j][2] * inv2, o[j][3] * inv2);
    }
}

// ----------------------------------------------------------------------------
// Launch  (my index 5 = first hgemm = ncu capture target)
// ----------------------------------------------------------------------------
extern "C" void kernel_launch(void* const* d_in, const int* in_sizes, int n_in,
                              void* d_out, int out_size)
{
    const float* x        = (const float*)d_in[0];
    const float* age      = (const float*)d_in[1];
    const int*   mod_idx  = (const int*)  d_in[2];
    const float* mod_age  = (const float*)d_in[3];
    const float* mod2     = (const float*)d_in[4];
    const float* mod3     = (const float*)d_in[5];
    const float* ln0_w    = (const float*)d_in[6];
    const float* ln0_b    = (const float*)d_in[7];
    const float* ln1_w    = (const float*)d_in[8];
    const float* ln1_b    = (const float*)d_in[9];
    const float* ln2_w    = (const float*)d_in[10];
    const float* ln2_b    = (const float*)d_in[11];
    const float* q_w      = (const float*)d_in[12];
    const float* q_b      = (const float*)d_in[13];
    const float* k_w      = (const float*)d_in[14];
    const float* k_b      = (const float*)d_in[15];
    const float* v_w      = (const float*)d_in[16];
    const float* v_b      = (const float*)d_in[17];
    const float* c_w      = (const float*)d_in[18];
    const float* c_b      = (const float*)d_in[19];
    const float* fc_w     = (const float*)d_in[20];
    const float* fc_b     = (const float*)d_in[21];
    const float* proj_w   = (const float*)d_in[22];
    const float* proj_b   = (const float*)d_in[23];
    float* out = (float*)d_out;

    float *p_x1;
    __half *p_qh, *p_kh, *p_vh, *p_xnh, *p_snh, *p_yh, *p_hh;
    __half *p_wq, *p_wk, *p_wv, *p_wc, *p_wfc, *p_wpr;
    cudaGetSymbolAddress((void**)&p_x1,  g_x1);
    cudaGetSymbolAddress((void**)&p_qh,  g_qh);
    cudaGetSymbolAddress((void**)&p_kh,  g_kh);
    cudaGetSymbolAddress((void**)&p_vh,  g_vh);
    cudaGetSymbolAddress((void**)&p_xnh, g_xnh);
    cudaGetSymbolAddress((void**)&p_snh, g_snh);
    cudaGetSymbolAddress((void**)&p_yh,  g_yh);
    cudaGetSymbolAddress((void**)&p_hh,  g_hh);
    cudaGetSymbolAddress((void**)&p_wq,  g_wq);
    cudaGetSymbolAddress((void**)&p_wk,  g_wk);
    cudaGetSymbolAddress((void**)&p_wv,  g_wv);
    cudaGetSymbolAddress((void**)&p_wc,  g_wc);
    cudaGetSymbolAddress((void**)&p_wfc, g_wfc);
    cudaGetSymbolAddress((void**)&p_wpr, g_wpr);

    const int WSQ = NE * NE, WFC = FCD * NE;
    dim3 g768(NE / 128, NTOK / 128);
    dim3 gfc(FCD / 128, NTOK / 128);
    dim3 ga(LM / 64, NH, NB);

    fuse_prep_kernel<<<NB, LS>>>(mod_idx, mod_age);                    // 0
    ln_kernel<<<NTOK, 256>>>(x, p_xnh, ln1_w, ln1_b);                  // 1
    fuse_ln_kernel<<<NTOK, 256>>>(mod2, mod3, p_snh, ln0_w, ln0_b);    // 2
    f2h_kernel<<<WSQ / 512, 256>>>(q_w, p_wq, WSQ);                    // 3
    f2h_kernel<<<WSQ / 512, 256>>>(k_w, p_wk, WSQ);                    // 4

    // index 5: first GEMM  <-- ncu capture target
    hgemm_kernel<3><<<g768, 256>>>(p_xnh, p_wq, q_b, nullptr, p_qh, NTOK, NE, NE);  // 5

    f2h_kernel<<<WSQ / 512, 256>>>(v_w, p_wv, WSQ);                    // 6
    hgemm_kernel<3><<<g768, 256>>>(p_snh, p_wk, k_b, nullptr, p_kh, NTOK, NE, NE);
    hgemm_kernel<3><<<g768, 256>>>(p_snh, p_wv, v_b, nullptr, p_vh, NTOK, NE, NE);

    attn_mma_kernel<<<ga, 128>>>(p_qh, p_kh, p_vh, age, mod_age, p_yh);

    f2h_kernel<<<WSQ / 512, 256>>>(c_w, p_wc, WSQ);
    hgemm_kernel<1><<<g768, 256>>>(p_yh, p_wc, c_b, x, p_x1, NTOK, NE, NE);

    ln_kernel<<<NTOK, 256>>>(p_x1, p_xnh, ln2_w, ln2_b);
    f2h_kernel<<<WFC / 512, 256>>>(fc_w, p_wfc, WFC);
    hgemm_kernel<2><<<gfc, 256>>>(p_xnh, p_wfc, fc_b, nullptr, p_hh, NTOK, FCD, NE);
    f2h_kernel<<<WFC / 512, 256>>>(proj_w, p_wpr, WFC);
    hgemm_kernel<1><<<g768, 256>>>(p_hh, p_wpr, proj_b, p_x1, out, NTOK, NE, FCD);
}

// round 11
// speedup vs baseline: 8.5391x; 1.0506x over previous
#include <cuda_runtime.h>
#include <cuda_fp16.h>
#include <math.h>
#include <stdint.h>

// ----------------------------------------------------------------------------
// Problem constants
// ----------------------------------------------------------------------------
#define NB 4
#define LM 1024
#define LS 1024
#define NE 768
#define NH 12
#define HD 64
#define HALF 512
#define NTOK (NB * LM)          // 4096
#define FCD (4 * NE)            // 3072
#define LN_EPS 1e-5f
#define FULLMASK 0xffffffffu

// ----------------------------------------------------------------------------
// Scratch (device globals -- no runtime allocation allowed)
// ----------------------------------------------------------------------------
__device__ float  g_x1[NTOK * NE];
__device__ __half g_qh [NTOK * NE];   // Q/K/V in fp16
__device__ __half g_kh [NTOK * NE];
__device__ __half g_vh [NTOK * NE];
__device__ __half g_xnh[NTOK * NE];   // LN outputs (fp16)
__device__ __half g_snh[NTOK * NE];
__device__ __half g_yh [NTOK * NE];   // attention out (fp16)
__device__ __half g_hh [NTOK * FCD]; // GELU activations (fp16)
__device__ __half g_wq [NE * NE];     // weights (fp16)
__device__ __half g_wk [NE * NE];
__device__ __half g_wv [NE * NE];
__device__ __half g_wc [NE * NE];
__device__ __half g_wfc[FCD * NE];
__device__ __half g_wpr[NE * FCD];
__device__ int g_src[NB * LS];

__device__ __forceinline__ uint32_t smem_u32(const void* p) {
    return (uint32_t)__cvta_generic_to_shared(p);
}

// ----------------------------------------------------------------------------
// Batched fp32 -> fp16 conversion: 6 segments in one launch.
// Each thread converts 8 elems (two float4 -> one uint4 of half2s).
// ----------------------------------------------------------------------------
__global__ void f2h6_kernel(const float* __restrict__ s0, const float* __restrict__ s1,
                            const float* __restrict__ s2, const float* __restrict__ s3,
                            const float* __restrict__ s4, const float* __restrict__ s5,
                            __half* __restrict__ d0, __half* __restrict__ d1,
                            __half* __restrict__ d2, __half* __restrict__ d3,
                            __half* __restrict__ d4, __half* __restrict__ d5,
                            int n_sq, int n_fc)
{
    const float* in; __half* out; int n;
    switch (blockIdx.y) {
        case 0: in = s0; out = d0; n = n_sq; break;
        case 1: in = s1; out = d1; n = n_sq; break;
        case 2: in = s2; out = d2; n = n_sq; break;
        case 3: in = s3; out = d3; n = n_sq; break;
        case 4: in = s4; out = d4; n = n_fc; break;
        default: in = s5; out = d5; n = n_fc; break;
    }
    int i = (blockIdx.x * 256 + threadIdx.x) * 8;
    if (i < n) {
        float4 a = *(const float4*)(in + i);
        float4 b = *(const float4*)(in + i + 4);
        __half2 h[4];
        h[0] = __floats2half2_rn(a.x, a.y);
        h[1] = __floats2half2_rn(a.z, a.w);
        h[2] = __floats2half2_rn(b.x, b.y);
        h[3] = __floats2half2_rn(b.z, b.w);
        *(uint4*)(out + i) = *(uint4*)h;
    }
}

// ----------------------------------------------------------------------------
// Kernel: stable argsort of mod_age + scatter bookkeeping (parallel scan).
// rank_j = #{i: a_i<a_j} + #{i<j: a_i==a_j}; then in sorted order,
// c2(j) = exclusive count of 2s (ballot prefix), c3(j) = j - c2(j).
// ----------------------------------------------------------------------------
__global__ void fuse_prep_kernel(const int* __restrict__ mod_idx,
                                 const float* __restrict__ mod_age)
{
    __shared__ float a[LS];
    __shared__ int   ord[LS];
    __shared__ int   sid[LS];
    __shared__ int   wsum[32];
    int b = blockIdx.x;
    int j = threadIdx.x;
    a[j] = mod_age[b * LS + j];
    __syncthreads();
    float aj = a[j];
    int r = 0;
    #pragma unroll 4
    for (int i = 0; i < LS; i++) {
        float ai = a[i];
        r += (ai < aj) || (ai == aj && i < j);
    }
    ord[r] = j;
    __syncthreads();
    sid[j] = mod_idx[b * LS + ord[j]];
    __syncthreads();

    int lane = j & 31, wid = j >> 5;
    int m2 = (sid[j] == 2);
    unsigned bal = __ballot_sync(FULLMASK, m2);
    int excl = __popc(bal & ((1u << lane) - 1));
    if (lane == 0) wsum[wid] = __popc(bal);
    __syncthreads();
    if (j < 32) {
        int v = wsum[j];
        int s = v;
        #pragma unroll
        for (int off = 1; off < 32; off <<= 1) {
            int t = __shfl_up_sync(FULLMASK, s, off);
            if (j >= off) s += t;
        }
        wsum[j] = s - v;   // exclusive
    }
    __syncthreads();
    int c2 = wsum[wid] + excl;
    int c3 = j - c2;
    int src;
    if (m2) src = b * HALF + min(c2, HALF - 1);
    else    src = (b * HALF + min(c3, HALF - 1)) | (1 << 30);
    g_src[b * LS + j] = src;
}

// ----------------------------------------------------------------------------
// LayerNorm over 768-wide rows -> fp16 output. 256 threads, 3 elems each.
// ----------------------------------------------------------------------------
__device__ __forceinline__ void ln_row_body(const float* __restrict__ p,
                                            __half* __restrict__ o,
                                            const float* __restrict__ w,
                                            const float* __restrict__ bb)
{
    int t = threadIdx.x;
    float x0 = p[t], x1 = p[t + 256], x2 = p[t + 512];
    float s = x0 + x1 + x2;
    float q = x0 * x0 + x1 * x1 + x2 * x2;
    #pragma unroll
    for (int off = 16; off; off >>= 1) {
        s += __shfl_down_sync(FULLMASK, s, off);
        q += __shfl_down_sync(FULLMASK, q, off);
    }
    __shared__ float ss[8], sq[8];
    __shared__ float mr[2];
    int wid = t >> 5, lane = t & 31;
    if (lane == 0) { ss[wid] = s; sq[wid] = q; }
    __syncthreads();
    if (t == 0) {
        float S = 0.f, Q = 0.f;
        #pragma unroll
        for (int i = 0; i < 8; i++) { S += ss[i]; Q += sq[i]; }
        float mean = S * (1.f / NE);
        float var  = Q * (1.f / NE) - mean * mean;
        mr[0] = mean;
        mr[1] = rsqrtf(var + LN_EPS);
    }
    __syncthreads();
    float mean = mr[0], rstd = mr[1];
    o[t]       = __float2half_rn((x0 - mean) * rstd * w[t]       + bb[t]);
    o[t + 256] = __float2half_rn((x1 - mean) * rstd * w[t + 256] + bb[t + 256]);
    o[t + 512] = __float2half_rn((x2 - mean) * rstd * w[t + 512] + bb[t + 512]);
}

__global__ void ln_kernel(const float* __restrict__ in, __half* __restrict__ out,
                          const float* __restrict__ w, const float* __restrict__ b)
{
    int row = blockIdx.x;
    ln_row_body(in + (size_t)row * NE, out + (size_t)row * NE, w, b);
}

__global__ void fuse_ln_kernel(const float* __restrict__ mod2,
                               const float* __restrict__ mod3,
                               __half* __restrict__ out,
                               const float* __restrict__ w, const float* __restrict__ b)
{
    int row = blockIdx.x;
    int s = g_src[row];
    const float* tab = (s & (1 << 30)) ? mod3 : mod2;
    const float* p = tab + (size_t)(s & 0x3FFFFFFF) * NE;
    ln_row_body(p, out + (size_t)row * NE, w, b);
}

// ----------------------------------------------------------------------------
// HMMA fp16 GEMM: 128x128x32, 3-stage cp.async, 1 barrier/iter.
// EPI: 0 = fp32 out; 1 = fp32 out + residual; 2 = gelu -> fp16; 3 = fp16 out
// ----------------------------------------------------------------------------
#define BM 128
#define BN 128
#define BK 32

__device__ __forceinline__ int sw_off(int r, int c) {
    return r * 64 + ((c ^ ((r >> 1) & 3)) << 4);
}

template<int EPI>
__global__ void __launch_bounds__(256, 2)
hgemm_kernel(const __half* __restrict__ A, const __half* __restrict__ W,
             const float* __restrict__ bias, const float* __restrict__ res,
             void* __restrict__ Cout, int M, int N, int K)
{
    __shared__ __align__(128) __half sA[3][BM * BK];
    __shared__ __align__(128) __half sB[3][BN * BK];

    const int tid = threadIdx.x;
    const int lane = tid & 31, wid = tid >> 5;
    const int warp_m = wid & 3, warp_n = wid >> 2;
    const int m0 = blockIdx.y * BM, n0 = blockIdx.x * BN;

    float acc[2][8][4];
    #pragma unroll
    for (int im = 0; im < 2; im++)
        #pragma unroll
        for (int jn = 0; jn < 8; jn++)
            #pragma unroll
            for (int r = 0; r < 4; r++) acc[im][jn][r] = 0.f;

    const int ld_row = tid >> 2;
    const int ld_sub = tid & 3;
    const int nk = K / BK;

    auto load_stage = [&](int s, int kt) {
        const __half* Ag = A + (size_t)m0 * K + kt * BK;
        const __half* Bg = W + (size_t)n0 * K + kt * BK;
        #pragma unroll
        for (int i = 0; i < 2; i++) {
            int row = ld_row + i * 64;
            int off = sw_off(row, ld_sub);
            uint32_t da = smem_u32((const uint8_t*)sA[s] + off);
            const void* ga = Ag + (size_t)row * K + ld_sub * 8;
            asm volatile("cp.async.cg.shared.global [%0], [%1], 16;" :: "r"(da), "l"(ga));
            uint32_t db = smem_u32((const uint8_t*)sB[s] + off);
            const void* gb = Bg + (size_t)row * K + ld_sub * 8;
            asm volatile("cp.async.cg.shared.global [%0], [%1], 16;" :: "r"(db), "l"(gb));
        }
    };

    load_stage(0, 0);
    asm volatile("cp.async.commit_group;" ::: "memory");
    load_stage(1, 1);
    asm volatile("cp.async.commit_group;" ::: "memory");

    const int a_r0 = warp_m * 32 + (lane & 15);
    const int a_ch = lane >> 4;
    const int b_r0 = warp_n * 64 + (lane & 7) + ((lane >> 4) << 3);
    const int b_ch = (lane >> 3) & 1;

    int buf = 0;
    for (int kt = 0; kt < nk; kt++) {
        asm volatile("cp.async.wait_group 1;" ::: "memory");
        __syncthreads();
        if (kt + 2 < nk) {
            int s2 = buf + 2; if (s2 >= 3) s2 -= 3;
            load_stage(s2, kt + 2);
        }
        asm volatile("cp.async.commit_group;" ::: "memory");

        const uint32_t baseA = smem_u32(sA[buf]);
        const uint32_t baseB = smem_u32(sB[buf]);

        #pragma unroll
        for (int ks = 0; ks < 2; ks++) {
            uint32_t af[2][4];
            #pragma unroll
            for (int im = 0; im < 2; im++) {
                int r = a_r0 + im * 16;
                uint32_t addr = baseA + sw_off(r, ks * 2 + a_ch);
                asm volatile("ldmatrix.sync.aligned.m8n8.x4.shared.b16 {%0,%1,%2,%3}, [%4];"
                             : "=r"(af[im][0]), "=r"(af[im][1]), "=r"(af[im][2]), "=r"(af[im][3])
                             : "r"(addr));
            }
            uint32_t bf[8][2];
            #pragma unroll
            for (int j4 = 0; j4 < 4; j4++) {
                uint32_t r0, r1, r2, r3;
                int r = b_r0 + j4 * 16;
                uint32_t addr = baseB + sw_off(r, ks * 2 + b_ch);
                asm volatile("ldmatrix.sync.aligned.m8n8.x4.shared.b16 {%0,%1,%2,%3}, [%4];"
                             : "=r"(r0), "=r"(r1), "=r"(r2), "=r"(r3) : "r"(addr));
                bf[2 * j4][0] = r0; bf[2 * j4][1] = r1;
                bf[2 * j4 + 1][0] = r2; bf[2 * j4 + 1][1] = r3;
            }
            #pragma unroll
            for (int im = 0; im < 2; im++)
                #pragma unroll
                for (int jn = 0; jn < 8; jn++) {
                    asm volatile(
                        "mma.sync.aligned.m16n8k16.row.col.f32.f16.f16.f32 "
                        "{%0,%1,%2,%3}, {%4,%5,%6,%7}, {%8,%9}, {%0,%1,%2,%3};"
                        : "+f"(acc[im][jn][0]), "+f"(acc[im][jn][1]),
                          "+f"(acc[im][jn][2]), "+f"(acc[im][jn][3])
                        : "r"(af[im][0]), "r"(af[im][1]), "r"(af[im][2]), "r"(af[im][3]),
                          "r"(bf[jn][0]), "r"(bf[jn][1]));
                }
        }
        buf++; if (buf == 3) buf = 0;
    }

    #pragma unroll
    for (int im = 0; im < 2; im++) {
        #pragma unroll
        for (int jn = 0; jn < 8; jn++) {
            int n = n0 + warp_n * 64 + jn * 8 + (lane & 3) * 2;
            float b0 = bias[n], b1 = bias[n + 1];
            #pragma unroll
            for (int rp = 0; rp < 2; rp++) {
                int m = m0 + warp_m * 32 + im * 16 + (lane >> 2) + 8 * rp;
                float v0 = acc[im][jn][2 * rp]     + b0;
                float v1 = acc[im][jn][2 * rp + 1] + b1;
                if (EPI == 1) {
                    const float* rr = res + (size_t)m * N + n;
                    v0 += rr[0]; v1 += rr[1];
                }
                if (EPI == 2) {
                    v0 = 0.5f * v0 * (1.f + erff(v0 * 0.70710678118654752f));
                    v1 = 0.5f * v1 * (1.f + erff(v1 * 0.70710678118654752f));
                }
                if (EPI == 2 || EPI == 3) {
                    *(__half2*)((__half*)Cout + (size_t)m * N + n) = __floats2half2_rn(v0, v1);
                } else {
                    *(float2*)((float*)Cout + (size_t)m * N + n) = make_float2(v0, v1);
                }
            }
        }
    }
}

// ----------------------------------------------------------------------------
// Tensorized flash attention (R10, validated). CTA = 64 q-rows, 4 warps.
// ----------------------------------------------------------------------------
__device__ __forceinline__ int swb(int r, int c) {
    return r * 128 + ((c ^ (r & 7)) << 4);
}

__global__ void __launch_bounds__(128)
attn_mma_kernel(const __half* __restrict__ Q, const __half* __restrict__ K,
                const __half* __restrict__ V, const float* __restrict__ age,
                const float* __restrict__ mage, __half* __restrict__ Y)
{
    const int b = blockIdx.z, h = blockIdx.y;
    const int q0 = blockIdx.x * 64;
    const int tid = threadIdx.x, wid = tid >> 5, lane = tid & 31;

    __shared__ __align__(128) __half sQ[64 * 64];
    __shared__ __align__(128) __half sK[2][64 * 64];
    __shared__ __align__(128) __half sV[2][64 * 64];
    __shared__ int s_km[64];

    #pragma unroll
    for (int i = 0; i < 4; i++) {
        int id = i * 128 + tid, r = id >> 3, c = id & 7;
        uint32_t d = smem_u32((uint8_t*)sQ + swb(r, c));
        const void* g = Q + ((size_t)(b * LM + q0 + r) * NE + h * HD + c * 8);
        asm volatile("cp.async.cg.shared.global [%0], [%1], 16;" :: "r"(d), "l"(g));
    }
    asm volatile("cp.async.commit_group;" ::: "memory");

    auto load_kv = [&](int s, int kt) {
        #pragma unroll
        for (int i = 0; i < 4; i++) {
            int id = i * 128 + tid, r = id >> 3, c = id & 7;
            size_t gofs = (size_t)(b * LS + kt + r) * NE + h * HD + c * 8;
            uint32_t dk = smem_u32((uint8_t*)sK[s] + swb(r, c));
            asm volatile("cp.async.cg.shared.global [%0], [%1], 16;" :: "r"(dk), "l"((const void*)(K + gofs)));
            uint32_t dv = smem_u32((uint8_t*)sV[s] + swb(r, c));
            asm volatile("cp.async.cg.shared.global [%0], [%1], 16;" :: "r"(dv), "l"((const void*)(V + gofs)));
        }
        asm volatile("cp.async.commit_group;" ::: "memory");
    };
    load_kv(0, 0);

    if (tid < 64) {
        float a = age[b * LM + q0 + tid];
        const float* ma = mage + b * LS;
        int lo = 0, hi = LS;
        while (lo < hi) {
            int mid = (lo + hi) >> 1;
            if (ma[mid] <= a) lo = mid + 1; else hi = mid;
        }
        s_km[tid] = lo;
    }
    __syncthreads();

    const int rq    = lane >> 2;
    const int km1   = s_km[wid * 16 + rq];
    const int km2   = s_km[wid * 16 + rq + 8];
    const int km_hi = s_km[wid * 16 + 15];
    const int nt    = (s_km[63] + 63) >> 6;

    float m1 = -INFINITY, m2 = -INFINITY, l1 = 0.f, l2 = 0.f;
    float o[8][4];
    #pragma unroll
    for (int j = 0; j < 8; j++)
        #pragma unroll
        for (int r = 0; r < 4; r++) o[j][r] = 0.f;
    uint32_t qf[4][4];

    for (int t = 0; t < nt; t++) {
        const int kt = t * 64;
        asm volatile("cp.async.wait_group 0;" ::: "memory");
        __syncthreads();
        if (t + 1 < nt) load_kv((t + 1) & 1, kt + 64);

        if (t == 0) {
            int ar = wid * 16 + (lane & 15);
            #pragma unroll
            for (int kc = 0; kc < 4; kc++) {
                uint32_t addr = smem_u32((uint8_t*)sQ + swb(ar, kc * 2 + (lane >> 4)));
                asm volatile("ldmatrix.sync.aligned.m8n8.x4.shared.b16 {%0,%1,%2,%3}, [%4];"
                             : "=r"(qf[kc][0]), "=r"(qf[kc][1]), "=r"(qf[kc][2]), "=r"(qf[kc][3])
                             : "r"(addr));
            }
        }

        if (kt < km_hi) {
            const int bufi = t & 1;
            float s[8][4];
            #pragma unroll
            for (int j = 0; j < 8; j++)
                #pragma unroll
                for (int r = 0; r < 4; r++) s[j][r] = 0.f;

            const int br = (lane & 7) + ((lane >> 4) << 3);
            const int bc = (lane >> 3) & 1;
            #pragma unroll
            for (int kc = 0; kc < 4; kc++) {
                uint32_t kf[8][2];
                #pragma unroll
                for (int j4 = 0; j4 < 4; j4++) {
                    uint32_t r0, r1, r2, r3;
                    int r = br + j4 * 16;
                    uint32_t addr = smem_u32((uint8_t*)sK[bufi] + swb(r, kc * 2 + bc));
                    asm volatile("ldmatrix.sync.aligned.m8n8.x4.shared.b16 {%0,%1,%2,%3}, [%4];"
                                 : "=r"(r0), "=r"(r1), "=r"(r2), "=r"(r3) : "r"(addr));
                    kf[2 * j4][0] = r0; kf[2 * j4][1] = r1;
                    kf[2 * j4 + 1][0] = r2; kf[2 * j4 + 1][1] = r3;
                }
                #pragma unroll
                for (int j = 0; j < 8; j++) {
                    asm volatile(
                        "mma.sync.aligned.m16n8k16.row.col.f32.f16.f16.f32 "
                        "{%0,%1,%2,%3}, {%4,%5,%6,%7}, {%8,%9}, {%0,%1,%2,%3};"
                        : "+f"(s[j][0]), "+f"(s[j][1]), "+f"(s[j][2]), "+f"(s[j][3])
                        : "r"(qf[kc][0]), "r"(qf[kc][1]), "r"(qf[kc][2]), "r"(qf[kc][3]),
                          "r"(kf[j][0]), "r"(kf[j][1]));
                }
            }

            const int colb = kt + 2 * (lane & 3);
            #pragma unroll
            for (int j = 0; j < 8; j++) {
                int c0 = colb + 8 * j;
                s[j][0] = (c0     < km1) ? s[j][0] * 0.125f : -INFINITY;
                s[j][1] = (c0 + 1 < km1) ? s[j][1] * 0.125f : -INFINITY;
                s[j][2] = (c0     < km2) ? s[j][2] * 0.125f : -INFINITY;
                s[j][3] = (c0 + 1 < km2) ? s[j][3] * 0.125f : -INFINITY;
            }

            float mt1 = -INFINITY, mt2 = -INFINITY;
            #pragma unroll
            for (int j = 0; j < 8; j++) {
                mt1 = fmaxf(mt1, fmaxf(s[j][0], s[j][1]));
                mt2 = fmaxf(mt2, fmaxf(s[j][2], s[j][3]));
            }
            mt1 = fmaxf(mt1, __shfl_xor_sync(FULLMASK, mt1, 1));
            mt1 = fmaxf(mt1, __shfl_xor_sync(FULLMASK, mt1, 2));
            mt2 = fmaxf(mt2, __shfl_xor_sync(FULLMASK, mt2, 1));
            mt2 = fmaxf(mt2, __shfl_xor_sync(FULLMASK, mt2, 2));
            float mn1 = fmaxf(m1, mt1), mn2 = fmaxf(m2, mt2);
            float ms1 = fmaxf(mn1, -1e30f), ms2 = fmaxf(mn2, -1e30f);
            float corr1 = __expf(m1 - ms1), corr2 = __expf(m2 - ms2);
            float ps1 = 0.f, ps2 = 0.f;
            #pragma unroll
            for (int j = 0; j < 8; j++) {
                s[j][0] = __expf(s[j][0] - ms1);
                s[j][1] = __expf(s[j][1] - ms1);
                s[j][2] = __expf(s[j][2] - ms2);
                s[j][3] = __expf(s[j][3] - ms2);
                ps1 += s[j][0] + s[j][1];
                ps2 += s[j][2] + s[j][3];
            }
            ps1 += __shfl_xor_sync(FULLMASK, ps1, 1);
            ps1 += __shfl_xor_sync(FULLMASK, ps1, 2);
            ps2 += __shfl_xor_sync(FULLMASK, ps2, 1);
            ps2 += __shfl_xor_sync(FULLMASK, ps2, 2);
            l1 = l1 * corr1 + ps1;
            l2 = l2 * corr2 + ps2;
            m1 = mn1; m2 = mn2;
            #pragma unroll
            for (int j = 0; j < 8; j++) {
                o[j][0] *= corr1; o[j][1] *= corr1;
                o[j][2] *= corr2; o[j][3] *= corr2;
            }

            const int vr0 = ((lane >> 3) & 1) * 8 + (lane & 7);
            #pragma unroll
            for (int kc = 0; kc < 4; kc++) {
                uint32_t pa[4];
                __half2* pah = (__half2*)pa;
                pah[0] = __floats2half2_rn(s[2 * kc][0], s[2 * kc][1]);
                pah[1] = __floats2half2_rn(s[2 * kc][2], s[2 * kc][3]);
                pah[2] = __floats2half2_rn(s[2 * kc + 1][0], s[2 * kc + 1][1]);
                pah[3] = __floats2half2_rn(s[2 * kc + 1][2], s[2 * kc + 1][3]);
                #pragma unroll
                for (int dg = 0; dg < 4; dg++) {
                    uint32_t v0, v1, v2, v3;
                    int r = kc * 16 + vr0;
                    uint32_t addr = smem_u32((uint8_t*)sV[bufi] + swb(r, dg * 2 + (lane >> 4)));
                    asm volatile("ldmatrix.sync.aligned.m8n8.x4.trans.shared.b16 {%0,%1,%2,%3}, [%4];"
                                 : "=r"(v0), "=r"(v1), "=r"(v2), "=r"(v3) : "r"(addr));
                    asm volatile(
                        "mma.sync.aligned.m16n8k16.row.col.f32.f16.f16.f32 "
                        "{%0,%1,%2,%3}, {%4,%5,%6,%7}, {%8,%9}, {%0,%1,%2,%3};"
                        : "+f"(o[2 * dg][0]), "+f"(o[2 * dg][1]), "+f"(o[2 * dg][2]), "+f"(o[2 * dg][3])
                        : "r"(pa[0]), "r"(pa[1]), "r"(pa[2]), "r"(pa[3]), "r"(v0), "r"(v1));
                    asm volatile(
                        "mma.sync.aligned.m16n8k16.row.col.f32.f16.f16.f32 "
                        "{%0,%1,%2,%3}, {%4,%5,%6,%7}, {%8,%9}, {%0,%1,%2,%3};"
                        : "+f"(o[2 * dg + 1][0]), "+f"(o[2 * dg + 1][1]), "+f"(o[2 * dg + 1][2]), "+f"(o[2 * dg + 1][3])
                        : "r"(pa[0]), "r"(pa[1]), "r"(pa[2]), "r"(pa[3]), "r"(v2), "r"(v3));
                }
            }
        }
    }

    float inv1 = (l1 > 0.f) ? (1.f / l1) : 0.f;
    float inv2 = (l2 > 0.f) ? (1.f / l2) : 0.f;
    size_t row1 = (size_t)(b * LM + q0 + wid * 16 + rq);
    #pragma unroll
    for (int j = 0; j < 8; j++) {
        int col = h * HD + 8 * j + 2 * (lane & 3);
        *(__half2*)(Y + row1 * NE + col)       = __floats2half2_rn(o[j][0] * inv1, o[j][1] * inv1);
        *(__half2*)(Y + (row1 + 8) * NE + col) = __floats2half2_rn(o[j][2] * inv2, o[j][3] * inv2);
    }
}

// ----------------------------------------------------------------------------
// Launch  (launch #3 = first hgemm = empirical ncu capture slot)
// ----------------------------------------------------------------------------
extern "C" void kernel_launch(void* const* d_in, const int* in_sizes, int n_in,
                              void* d_out, int out_size)
{
    const float* x        = (const float*)d_in[0];
    const float* age      = (const float*)d_in[1];
    const int*   mod_idx  = (const int*)  d_in[2];
    const float* mod_age  = (const float*)d_in[3];
    const float* mod2     = (const float*)d_in[4];
    const float* mod3     = (const float*)d_in[5];
    const float* ln0_w    = (const float*)d_in[6];
    const float* ln0_b    = (const float*)d_in[7];
    const float* ln1_w    = (const float*)d_in[8];
    const float* ln1_b    = (const float*)d_in[9];
    const float* ln2_w    = (const float*)d_in[10];
    const float* ln2_b    = (const float*)d_in[11];
    const float* q_w      = (const float*)d_in[12];
    const float* q_b      = (const float*)d_in[13];
    const float* k_w      = (const float*)d_in[14];
    const float* k_b      = (const float*)d_in[15];
    const float* v_w      = (const float*)d_in[16];
    const float* v_b      = (const float*)d_in[17];
    const float* c_w      = (const float*)d_in[18];
    const float* c_b      = (const float*)d_in[19];
    const float* fc_w     = (const float*)d_in[20];
    const float* fc_b     = (const float*)d_in[21];
    const float* proj_w   = (const float*)d_in[22];
    const float* proj_b   = (const float*)d_in[23];
    float* out = (float*)d_out;

    float *p_x1;
    __half *p_qh, *p_kh, *p_vh, *p_xnh, *p_snh, *p_yh, *p_hh;
    __half *p_wq, *p_wk, *p_wv, *p_wc, *p_wfc, *p_wpr;
    cudaGetSymbolAddress((void**)&p_x1,  g_x1);
    cudaGetSymbolAddress((void**)&p_qh,  g_qh);
    cudaGetSymbolAddress((void**)&p_kh,  g_kh);
    cudaGetSymbolAddress((void**)&p_vh,  g_vh);
    cudaGetSymbolAddress((void**)&p_xnh, g_xnh);
    cudaGetSymbolAddress((void**)&p_snh, g_snh);
    cudaGetSymbolAddress((void**)&p_yh,  g_yh);
    cudaGetSymbolAddress((void**)&p_hh,  g_hh);
    cudaGetSymbolAddress((void**)&p_wq,  g_wq);
    cudaGetSymbolAddress((void**)&p_wk,  g_wk);
    cudaGetSymbolAddress((void**)&p_wv,  g_wv);
    cudaGetSymbolAddress((void**)&p_wc,  g_wc);
    cudaGetSymbolAddress((void**)&p_wfc, g_wfc);
    cudaGetSymbolAddress((void**)&p_wpr, g_wpr);

    const int WSQ = NE * NE, WFC = FCD * NE;
    dim3 g768(NE / 128, NTOK / 128);
    dim3 gfc(FCD / 128, NTOK / 128);
    dim3 ga(LM / 64, NH, NB);
    dim3 gcv(WFC / 2048, 6);

    // 0: scatter prep   1: LN(x)   2: all weight converts
    fuse_prep_kernel<<<NB, LS>>>(mod_idx, mod_age);                               // 0
    ln_kernel<<<NTOK, 256>>>(x, p_xnh, ln1_w, ln1_b);                             // 1
    f2h6_kernel<<<gcv, 256>>>(q_w, k_w, v_w, c_w, fc_w, proj_w,
                              p_wq, p_wk, p_wv, p_wc, p_wfc, p_wpr, WSQ, WFC);    // 2

    // 3: first GEMM  <-- ncu capture slot (empirical)
    hgemm_kernel<3><<<g768, 256>>>(p_xnh, p_wq, q_b, nullptr, p_qh, NTOK, NE, NE); // 3

    fuse_ln_kernel<<<NTOK, 256>>>(mod2, mod3, p_snh, ln0_w, ln0_b);               // 4
    hgemm_kernel<3><<<g768, 256>>>(p_snh, p_wk, k_b, nullptr, p_kh, NTOK, NE, NE); // 5
    hgemm_kernel<3><<<g768, 256>>>(p_snh, p_wv, v_b, nullptr, p_vh, NTOK, NE, NE); // 6

    attn_mma_kernel<<<ga, 128>>>(p_qh, p_kh, p_vh, age, mod_age, p_yh);           // 7

    hgemm_kernel<1><<<g768, 256>>>(p_yh, p_wc, c_b, x, p_x1, NTOK, NE, NE);       // 8
    ln_kernel<<<NTOK, 256>>>(p_x1, p_xnh, ln2_w, ln2_b);                          // 9
    hgemm_kernel<2><<<gfc, 256>>>(p_xnh, p_wfc, fc_b, nullptr, p_hh, NTOK, FCD, NE); // 10
    hgemm_kernel<1><<<g768, 256>>>(p_hh, p_wpr, proj_b, p_x1, out, NTOK, NE, FCD);   // 11
}

// round 12
// speedup vs baseline: 8.8174x; 1.0326x over previous
#include <cuda_runtime.h>
#include <cuda_fp16.h>
#include <math.h>
#include <stdint.h>

// ----------------------------------------------------------------------------
// Problem constants
// ----------------------------------------------------------------------------
#define NB 4
#define LM 1024
#define LS 1024
#define NE 768
#define NH 12
#define HD 64
#define HALF 512
#define NTOK (NB * LM)          // 4096
#define FCD (4 * NE)            // 3072
#define LN_EPS 1e-5f
#define FULLMASK 0xffffffffu

// ----------------------------------------------------------------------------
// Scratch (device globals -- no runtime allocation allowed)
// ----------------------------------------------------------------------------
__device__ float  g_x1[NTOK * NE];
__device__ __half g_qh [NTOK * NE];   // Q/K/V in fp16
__device__ __half g_kh [NTOK * NE];
__device__ __half g_vh [NTOK * NE];
__device__ __half g_xnh[NTOK * NE];   // LN outputs (fp16)
__device__ __half g_snh[NTOK * NE];
__device__ __half g_yh [NTOK * NE];   // attention out (fp16)
__device__ __half g_hh [NTOK * FCD]; // GELU activations (fp16)
__device__ __half g_wq [NE * NE];     // weights (fp16)
__device__ __half g_wk [NE * NE];
__device__ __half g_wv [NE * NE];
__device__ __half g_wc [NE * NE];
__device__ __half g_wfc[FCD * NE];
__device__ __half g_wpr[NE * FCD];
__device__ int g_src[NB * LS];

__device__ __forceinline__ uint32_t smem_u32(const void* p) {
    return (uint32_t)__cvta_generic_to_shared(p);
}

// ----------------------------------------------------------------------------
// Batched fp32 -> fp16 conversion: 6 segments in one launch.
// ----------------------------------------------------------------------------
__global__ void f2h6_kernel(const float* __restrict__ s0, const float* __restrict__ s1,
                            const float* __restrict__ s2, const float* __restrict__ s3,
                            const float* __restrict__ s4, const float* __restrict__ s5,
                            __half* __restrict__ d0, __half* __restrict__ d1,
                            __half* __restrict__ d2, __half* __restrict__ d3,
                            __half* __restrict__ d4, __half* __restrict__ d5,
                            int n_sq, int n_fc)
{
    const float* in; __half* out; int n;
    switch (blockIdx.y) {
        case 0: in = s0; out = d0; n = n_sq; break;
        case 1: in = s1; out = d1; n = n_sq; break;
        case 2: in = s2; out = d2; n = n_sq; break;
        case 3: in = s3; out = d3; n = n_sq; break;
        case 4: in = s4; out = d4; n = n_fc; break;
        default: in = s5; out = d5; n = n_fc; break;
    }
    int i = (blockIdx.x * 256 + threadIdx.x) * 8;
    if (i < n) {
        float4 a = *(const float4*)(in + i);
        float4 b = *(const float4*)(in + i + 4);
        __half2 h[4];
        h[0] = __floats2half2_rn(a.x, a.y);
        h[1] = __floats2half2_rn(a.z, a.w);
        h[2] = __floats2half2_rn(b.x, b.y);
        h[3] = __floats2half2_rn(b.z, b.w);
        *(uint4*)(out + i) = *(uint4*)h;
    }
}

// ----------------------------------------------------------------------------
// Stable argsort of mod_age + scatter bookkeeping (parallel ballot scan).
// ----------------------------------------------------------------------------
__global__ void fuse_prep_kernel(const int* __restrict__ mod_idx,
                                 const float* __restrict__ mod_age)
{
    __shared__ float a[LS];
    __shared__ int   ord[LS];
    __shared__ int   sid[LS];
    __shared__ int   wsum[32];
    int b = blockIdx.x;
    int j = threadIdx.x;
    a[j] = mod_age[b * LS + j];
    __syncthreads();
    float aj = a[j];
    int r = 0;
    #pragma unroll 4
    for (int i = 0; i < LS; i++) {
        float ai = a[i];
        r += (ai < aj) || (ai == aj && i < j);
    }
    ord[r] = j;
    __syncthreads();
    sid[j] = mod_idx[b * LS + ord[j]];
    __syncthreads();

    int lane = j & 31, wid = j >> 5;
    int m2 = (sid[j] == 2);
    unsigned bal = __ballot_sync(FULLMASK, m2);
    int excl = __popc(bal & ((1u << lane) - 1));
    if (lane == 0) wsum[wid] = __popc(bal);
    __syncthreads();
    if (j < 32) {
        int v = wsum[j];
        int s = v;
        #pragma unroll
        for (int off = 1; off < 32; off <<= 1) {
            int t = __shfl_up_sync(FULLMASK, s, off);
            if (j >= off) s += t;
        }
        wsum[j] = s - v;
    }
    __syncthreads();
    int c2 = wsum[wid] + excl;
    int c3 = j - c2;
    int src;
    if (m2) src = b * HALF + min(c2, HALF - 1);
    else    src = (b * HALF + min(c3, HALF - 1)) | (1 << 30);
    g_src[b * LS + j] = src;
}

// ----------------------------------------------------------------------------
// LayerNorm over 768-wide rows -> fp16 output. 256 threads, 3 elems each.
// ----------------------------------------------------------------------------
__device__ __forceinline__ void ln_row_body(const float* __restrict__ p,
                                            __half* __restrict__ o,
                                            const float* __restrict__ w,
                                            const float* __restrict__ bb)
{
    int t = threadIdx.x;
    float x0 = p[t], x1 = p[t + 256], x2 = p[t + 512];
    float s = x0 + x1 + x2;
    float q = x0 * x0 + x1 * x1 + x2 * x2;
    #pragma unroll
    for (int off = 16; off; off >>= 1) {
        s += __shfl_down_sync(FULLMASK, s, off);
        q += __shfl_down_sync(FULLMASK, q, off);
    }
    __shared__ float ss[8], sq[8];
    __shared__ float mr[2];
    int wid = t >> 5, lane = t & 31;
    if (lane == 0) { ss[wid] = s; sq[wid] = q; }
    __syncthreads();
    if (t == 0) {
        float S = 0.f, Q = 0.f;
        #pragma unroll
        for (int i = 0; i < 8; i++) { S += ss[i]; Q += sq[i]; }
        float mean = S * (1.f / NE);
        float var  = Q * (1.f / NE) - mean * mean;
        mr[0] = mean;
        mr[1] = rsqrtf(var + LN_EPS);
    }
    __syncthreads();
    float mean = mr[0], rstd = mr[1];
    o[t]       = __float2half_rn((x0 - mean) * rstd * w[t]       + bb[t]);
    o[t + 256] = __float2half_rn((x1 - mean) * rstd * w[t + 256] + bb[t + 256]);
    o[t + 512] = __float2half_rn((x2 - mean) * rstd * w[t + 512] + bb[t + 512]);
}

__global__ void ln_kernel(const float* __restrict__ in, __half* __restrict__ out,
                          const float* __restrict__ w, const float* __restrict__ b)
{
    int row = blockIdx.x;
    ln_row_body(in + (size_t)row * NE, out + (size_t)row * NE, w, b);
}

__global__ void fuse_ln_kernel(const float* __restrict__ mod2,
                               const float* __restrict__ mod3,
                               __half* __restrict__ out,
                               const float* __restrict__ w, const float* __restrict__ b)
{
    int row = blockIdx.x;
    int s = g_src[row];
    const float* tab = (s & (1 << 30)) ? mod3 : mod2;
    const float* p = tab + (size_t)(s & 0x3FFFFFFF) * NE;
    ln_row_body(p, out + (size_t)row * NE, w, b);
}

// ----------------------------------------------------------------------------
// HMMA fp16 GEMM, templated M-tile: BM = 64*MI, BN=128, BK=32.
// 256 threads, warp grid 4(m) x 2(n), warp tile (16*MI) x 64.
// 3-stage cp.async, 1 barrier/iter. MI=1 -> 3 CTAs/SM target; MI=2 -> 2.
// EPI: 0 = fp32 out; 1 = fp32 out + residual; 2 = gelu -> fp16; 3 = fp16 out
// ----------------------------------------------------------------------------
#define BN 128
#define BK 32

__device__ __forceinline__ int sw_off(int r, int c) {
    return r * 64 + ((c ^ ((r >> 1) & 3)) << 4);
}

template<int EPI, int MI>
__global__ void __launch_bounds__(256, 4 - MI)
hgemm_kernel(const __half* __restrict__ A, const __half* __restrict__ W,
             const float* __restrict__ bias, const float* __restrict__ res,
             void* __restrict__ Cout, int M, int N, int K)
{
    constexpr int BM = 64 * MI;
    __shared__ __align__(128) __half sA[3][BM * BK];
    __shared__ __align__(128) __half sB[3][BN * BK];

    const int tid = threadIdx.x;
    const int lane = tid & 31, wid = tid >> 5;
    const int warp_m = wid & 3, warp_n = wid >> 2;
    const int m0 = blockIdx.y * BM, n0 = blockIdx.x * BN;

    float acc[MI][8][4];
    #pragma unroll
    for (int im = 0; im < MI; im++)
        #pragma unroll
        for (int jn = 0; jn < 8; jn++)
            #pragma unroll
            for (int r = 0; r < 4; r++) acc[im][jn][r] = 0.f;

    const int ld_row = tid >> 2;
    const int ld_sub = tid & 3;
    const int nk = K / BK;

    auto load_stage = [&](int s, int kt) {
        const __half* Ag = A + (size_t)m0 * K + kt * BK;
        const __half* Bg = W + (size_t)n0 * K + kt * BK;
        #pragma unroll
        for (int i = 0; i < MI; i++) {
            int row = ld_row + i * 64;
            int off = sw_off(row, ld_sub);
            uint32_t da = smem_u32((const uint8_t*)sA[s] + off);
            const void* ga = Ag + (size_t)row * K + ld_sub * 8;
            asm volatile("cp.async.cg.shared.global [%0], [%1], 16;" :: "r"(da), "l"(ga));
        }
        #pragma unroll
        for (int i = 0; i < 2; i++) {
            int row = ld_row + i * 64;
            int off = sw_off(row, ld_sub);
            uint32_t db = smem_u32((const uint8_t*)sB[s] + off);
            const void* gb = Bg + (size_t)row * K + ld_sub * 8;
            asm volatile("cp.async.cg.shared.global [%0], [%1], 16;" :: "r"(db), "l"(gb));
        }
    };

    load_stage(0, 0);
    asm volatile("cp.async.commit_group;" ::: "memory");
    load_stage(1, 1);
    asm volatile("cp.async.commit_group;" ::: "memory");

    const int a_r0 = warp_m * (16 * MI) + (lane & 15);
    const int a_ch = lane >> 4;
    const int b_r0 = warp_n * 64 + (lane & 7) + ((lane >> 4) << 3);
    const int b_ch = (lane >> 3) & 1;

    int buf = 0;
    for (int kt = 0; kt < nk; kt++) {
        asm volatile("cp.async.wait_group 1;" ::: "memory");
        __syncthreads();
        if (kt + 2 < nk) {
            int s2 = buf + 2; if (s2 >= 3) s2 -= 3;
            load_stage(s2, kt + 2);
        }
        asm volatile("cp.async.commit_group;" ::: "memory");

        const uint32_t baseA = smem_u32(sA[buf]);
        const uint32_t baseB = smem_u32(sB[buf]);

        #pragma unroll
        for (int ks = 0; ks < 2; ks++) {
            uint32_t af[MI][4];
            #pragma unroll
            for (int im = 0; im < MI; im++) {
                int r = a_r0 + im * 16;
                uint32_t addr = baseA + sw_off(r, ks * 2 + a_ch);
                asm volatile("ldmatrix.sync.aligned.m8n8.x4.shared.b16 {%0,%1,%2,%3}, [%4];"
                             : "=r"(af[im][0]), "=r"(af[im][1]), "=r"(af[im][2]), "=r"(af[im][3])
                             : "r"(addr));
            }
            uint32_t bf[8][2];
            #pragma unroll
            for (int j4 = 0; j4 < 4; j4++) {
                uint32_t r0, r1, r2, r3;
                int r = b_r0 + j4 * 16;
                uint32_t addr = baseB + sw_off(r, ks * 2 + b_ch);
                asm volatile("ldmatrix.sync.aligned.m8n8.x4.shared.b16 {%0,%1,%2,%3}, [%4];"
                             : "=r"(r0), "=r"(r1), "=r"(r2), "=r"(r3) : "r"(addr));
                bf[2 * j4][0] = r0; bf[2 * j4][1] = r1;
                bf[2 * j4 + 1][0] = r2; bf[2 * j4 + 1][1] = r3;
            }
            #pragma unroll
            for (int im = 0; im < MI; im++)
                #pragma unroll
                for (int jn = 0; jn < 8; jn++) {
                    asm volatile(
                        "mma.sync.aligned.m16n8k16.row.col.f32.f16.f16.f32 "
                        "{%0,%1,%2,%3}, {%4,%5,%6,%7}, {%8,%9}, {%0,%1,%2,%3};"
                        : "+f"(acc[im][jn][0]), "+f"(acc[im][jn][1]),
                          "+f"(acc[im][jn][2]), "+f"(acc[im][jn][3])
                        : "r"(af[im][0]), "r"(af[im][1]), "r"(af[im][2]), "r"(af[im][3]),
                          "r"(bf[jn][0]), "r"(bf[jn][1]));
                }
        }
        buf++; if (buf == 3) buf = 0;
    }

    #pragma unroll
    for (int im = 0; im < MI; im++) {
        #pragma unroll
        for (int jn = 0; jn < 8; jn++) {
            int n = n0 + warp_n * 64 + jn * 8 + (lane & 3) * 2;
            float b0 = bias[n], b1 = bias[n + 1];
            #pragma unroll
            for (int rp = 0; rp < 2; rp++) {
                int m = m0 + warp_m * (16 * MI) + im * 16 + (lane >> 2) + 8 * rp;
                float v0 = acc[im][jn][2 * rp]     + b0;
                float v1 = acc[im][jn][2 * rp + 1] + b1;
                if (EPI == 1) {
                    const float* rr = res + (size_t)m * N + n;
                    v0 += rr[0]; v1 += rr[1];
                }
                if (EPI == 2) {
                    v0 = 0.5f * v0 * (1.f + erff(v0 * 0.70710678118654752f));
                    v1 = 0.5f * v1 * (1.f + erff(v1 * 0.70710678118654752f));
                }
                if (EPI == 2 || EPI == 3) {
                    *(__half2*)((__half*)Cout + (size_t)m * N + n) = __floats2half2_rn(v0, v1);
                } else {
                    *(float2*)((float*)Cout + (size_t)m * N + n) = make_float2(v0, v1);
                }
            }
        }
    }
}

// ----------------------------------------------------------------------------
// Tensorized flash attention (R10, validated). CTA = 64 q-rows, 4 warps.
// ----------------------------------------------------------------------------
__device__ __forceinline__ int swb(int r, int c) {
    return r * 128 + ((c ^ (r & 7)) << 4);
}

__global__ void __launch_bounds__(128)
attn_mma_kernel(const __half* __restrict__ Q, const __half* __restrict__ K,
                const __half* __restrict__ V, const float* __restrict__ age,
                const float* __restrict__ mage, __half* __restrict__ Y)
{
    const int b = blockIdx.z, h = blockIdx.y;
    const int q0 = blockIdx.x * 64;
    const int tid = threadIdx.x, wid = tid >> 5, lane = tid & 31;

    __shared__ __align__(128) __half sQ[64 * 64];
    __shared__ __align__(128) __half sK[2][64 * 64];
    __shared__ __align__(128) __half sV[2][64 * 64];
    __shared__ int s_km[64];

    #pragma unroll
    for (int i = 0; i < 4; i++) {
        int id = i * 128 + tid, r = id >> 3, c = id & 7;
        uint32_t d = smem_u32((uint8_t*)sQ + swb(r, c));
        const void* g = Q + ((size_t)(b * LM + q0 + r) * NE + h * HD + c * 8);
        asm volatile("cp.async.cg.shared.global [%0], [%1], 16;" :: "r"(d), "l"(g));
    }
    asm volatile("cp.async.commit_group;" ::: "memory");

    auto load_kv = [&](int s, int kt) {
        #pragma unroll
        for (int i = 0; i < 4; i++) {
            int id = i * 128 + tid, r = id >> 3, c = id & 7;
            size_t gofs = (size_t)(b * LS + kt + r) * NE + h * HD + c * 8;
            uint32_t dk = smem_u32((uint8_t*)sK[s] + swb(r, c));
            asm volatile("cp.async.cg.shared.global [%0], [%1], 16;" :: "r"(dk), "l"((const void*)(K + gofs)));
            uint32_t dv = smem_u32((uint8_t*)sV[s] + swb(r, c));
            asm volatile("cp.async.cg.shared.global [%0], [%1], 16;" :: "r"(dv), "l"((const void*)(V + gofs)));
        }
        asm volatile("cp.async.commit_group;" ::: "memory");
    };
    load_kv(0, 0);

    if (tid < 64) {
        float a = age[b * LM + q0 + tid];
        const float* ma = mage + b * LS;
        int lo = 0, hi = LS;
        while (lo < hi) {
            int mid = (lo + hi) >> 1;
            if (ma[mid] <= a) lo = mid + 1; else hi = mid;
        }
        s_km[tid] = lo;
    }
    __syncthreads();

    const int rq    = lane >> 2;
    const int km1   = s_km[wid * 16 + rq];
    const int km2   = s_km[wid * 16 + rq + 8];
    const int km_hi = s_km[wid * 16 + 15];
    const int nt    = (s_km[63] + 63) >> 6;

    float m1 = -INFINITY, m2 = -INFINITY, l1 = 0.f, l2 = 0.f;
    float o[8][4];
    #pragma unroll
    for (int j = 0; j < 8; j++)
        #pragma unroll
        for (int r = 0; r < 4; r++) o[j][r] = 0.f;
    uint32_t qf[4][4];

    for (int t = 0; t < nt; t++) {
        const int kt = t * 64;
        asm volatile("cp.async.wait_group 0;" ::: "memory");
        __syncthreads();
        if (t + 1 < nt) load_kv((t + 1) & 1, kt + 64);

        if (t == 0) {
            int ar = wid * 16 + (lane & 15);
            #pragma unroll
            for (int kc = 0; kc < 4; kc++) {
                uint32_t addr = smem_u32((uint8_t*)sQ + swb(ar, kc * 2 + (lane >> 4)));
                asm volatile("ldmatrix.sync.aligned.m8n8.x4.shared.b16 {%0,%1,%2,%3}, [%4];"
                             : "=r"(qf[kc][0]), "=r"(qf[kc][1]), "=r"(qf[kc][2]), "=r"(qf[kc][3])
                             : "r"(addr));
            }
        }

        if (kt < km_hi) {
            const int bufi = t & 1;
            float s[8][4];
            #pragma unroll
            for (int j = 0; j < 8; j++)
                #pragma unroll
                for (int r = 0; r < 4; r++) s[j][r] = 0.f;

            const int br = (lane & 7) + ((lane >> 4) << 3);
            const int bc = (lane >> 3) & 1;
            #pragma unroll
            for (int kc = 0; kc < 4; kc++) {
                uint32_t kf[8][2];
                #pragma unroll
                for (int j4 = 0; j4 < 4; j4++) {
                    uint32_t r0, r1, r2, r3;
                    int r = br + j4 * 16;
                    uint32_t addr = smem_u32((uint8_t*)sK[bufi] + swb(r, kc * 2 + bc));
                    asm volatile("ldmatrix.sync.aligned.m8n8.x4.shared.b16 {%0,%1,%2,%3}, [%4];"
                                 : "=r"(r0), "=r"(r1), "=r"(r2), "=r"(r3) : "r"(addr));
                    kf[2 * j4][0] = r0; kf[2 * j4][1] = r1;
                    kf[2 * j4 + 1][0] = r2; kf[2 * j4 + 1][1] = r3;
                }
                #pragma unroll
                for (int j = 0; j < 8; j++) {
                    asm volatile(
                        "mma.sync.aligned.m16n8k16.row.col.f32.f16.f16.f32 "
                        "{%0,%1,%2,%3}, {%4,%5,%6,%7}, {%8,%9}, {%0,%1,%2,%3};"
                        : "+f"(s[j][0]), "+f"(s[j][1]), "+f"(s[j][2]), "+f"(s[j][3])
                        : "r"(qf[kc][0]), "r"(qf[kc][1]), "r"(qf[kc][2]), "r"(qf[kc][3]),
                          "r"(kf[j][0]), "r"(kf[j][1]));
                }
            }

            const int colb = kt + 2 * (lane & 3);
            #pragma unroll
            for (int j = 0; j < 8; j++) {
                int c0 = colb + 8 * j;
                s[j][0] = (c0     < km1) ? s[j][0] * 0.125f : -INFINITY;
                s[j][1] = (c0 + 1 < km1) ? s[j][1] * 0.125f : -INFINITY;
                s[j][2] = (c0     < km2) ? s[j][2] * 0.125f : -INFINITY;
                s[j][3] = (c0 + 1 < km2) ? s[j][3] * 0.125f : -INFINITY;
            }

            float mt1 = -INFINITY, mt2 = -INFINITY;
            #pragma unroll
            for (int j = 0; j < 8; j++) {
                mt1 = fmaxf(mt1, fmaxf(s[j][0], s[j][1]));
                mt2 = fmaxf(mt2, fmaxf(s[j][2], s[j][3]));
            }
            mt1 = fmaxf(mt1, __shfl_xor_sync(FULLMASK, mt1, 1));
            mt1 = fmaxf(mt1, __shfl_xor_sync(FULLMASK, mt1, 2));
            mt2 = fmaxf(mt2, __shfl_xor_sync(FULLMASK, mt2, 1));
            mt2 = fmaxf(mt2, __shfl_xor_sync(FULLMASK, mt2, 2));
            float mn1 = fmaxf(m1, mt1), mn2 = fmaxf(m2, mt2);
            float ms1 = fmaxf(mn1, -1e30f), ms2 = fmaxf(mn2, -1e30f);
            float corr1 = __expf(m1 - ms1), corr2 = __expf(m2 - ms2);
            float ps1 = 0.f, ps2 = 0.f;
            #pragma unroll
            for (int j = 0; j < 8; j++) {
                s[j][0] = __expf(s[j][0] - ms1);
                s[j][1] = __expf(s[j][1] - ms1);
                s[j][2] = __expf(s[j][2] - ms2);
                s[j][3] = __expf(s[j][3] - ms2);
                ps1 += s[j][0] + s[j][1];
                ps2 += s[j][2] + s[j][3];
            }
            ps1 += __shfl_xor_sync(FULLMASK, ps1, 1);
            ps1 += __shfl_xor_sync(FULLMASK, ps1, 2);
            ps2 += __shfl_xor_sync(FULLMASK, ps2, 1);
            ps2 += __shfl_xor_sync(FULLMASK, ps2, 2);
            l1 = l1 * corr1 + ps1;
            l2 = l2 * corr2 + ps2;
            m1 = mn1; m2 = mn2;
            #pragma unroll
            for (int j = 0; j < 8; j++) {
                o[j][0] *= corr1; o[j][1] *= corr1;
                o[j][2] *= corr2; o[j][3] *= corr2;
            }

            const int vr0 = ((lane >> 3) & 1) * 8 + (lane & 7);
            #pragma unroll
            for (int kc = 0; kc < 4; kc++) {
                uint32_t pa[4];
                __half2* pah = (__half2*)pa;
                pah[0] = __floats2half2_rn(s[2 * kc][0], s[2 * kc][1]);
                pah[1] = __floats2half2_rn(s[2 * kc][2], s[2 * kc][3]);
                pah[2] = __floats2half2_rn(s[2 * kc + 1][0], s[2 * kc + 1][1]);
                pah[3] = __floats2half2_rn(s[2 * kc + 1][2], s[2 * kc + 1][3]);
                #pragma unroll
                for (int dg = 0; dg < 4; dg++) {
                    uint32_t v0, v1, v2, v3;
                    int r = kc * 16 + vr0;
                    uint32_t addr = smem_u32((uint8_t*)sV[bufi] + swb(r, dg * 2 + (lane >> 4)));
                    asm volatile("ldmatrix.sync.aligned.m8n8.x4.trans.shared.b16 {%0,%1,%2,%3}, [%4];"
                                 : "=r"(v0), "=r"(v1), "=r"(v2), "=r"(v3) : "r"(addr));
                    asm volatile(
                        "mma.sync.aligned.m16n8k16.row.col.f32.f16.f16.f32 "
                        "{%0,%1,%2,%3}, {%4,%5,%6,%7}, {%8,%9}, {%0,%1,%2,%3};"
                        : "+f"(o[2 * dg][0]), "+f"(o[2 * dg][1]), "+f"(o[2 * dg][2]), "+f"(o[2 * dg][3])
                        : "r"(pa[0]), "r"(pa[1]), "r"(pa[2]), "r"(pa[3]), "r"(v0), "r"(v1));
                    asm volatile(
                        "mma.sync.aligned.m16n8k16.row.col.f32.f16.f16.f32 "
                        "{%0,%1,%2,%3}, {%4,%5,%6,%7}, {%8,%9}, {%0,%1,%2,%3};"
                        : "+f"(o[2 * dg + 1][0]), "+f"(o[2 * dg + 1][1]), "+f"(o[2 * dg + 1][2]), "+f"(o[2 * dg + 1][3])
                        : "r"(pa[0]), "r"(pa[1]), "r"(pa[2]), "r"(pa[3]), "r"(v2), "r"(v3));
                }
            }
        }
    }

    float inv1 = (l1 > 0.f) ? (1.f / l1) : 0.f;
    float inv2 = (l2 > 0.f) ? (1.f / l2) : 0.f;
    size_t row1 = (size_t)(b * LM + q0 + wid * 16 + rq);
    #pragma unroll
    for (int j = 0; j < 8; j++) {
        int col = h * HD + 8 * j + 2 * (lane & 3);
        *(__half2*)(Y + row1 * NE + col)       = __floats2half2_rn(o[j][0] * inv1, o[j][1] * inv1);
        *(__half2*)(Y + (row1 + 8) * NE + col) = __floats2half2_rn(o[j][2] * inv2, o[j][3] * inv2);
    }
}

// ----------------------------------------------------------------------------
// Launch  (launch #3 = first hgemm = empirical ncu capture slot)
// ----------------------------------------------------------------------------
extern "C" void kernel_launch(void* const* d_in, const int* in_sizes, int n_in,
                              void* d_out, int out_size)
{
    const float* x        = (const float*)d_in[0];
    const float* age      = (const float*)d_in[1];
    const int*   mod_idx  = (const int*)  d_in[2];
    const float* mod_age  = (const float*)d_in[3];
    const float* mod2     = (const float*)d_in[4];
    const float* mod3     = (const float*)d_in[5];
    const float* ln0_w    = (const float*)d_in[6];
    const float* ln0_b    = (const float*)d_in[7];
    const float* ln1_w    = (const float*)d_in[8];
    const float* ln1_b    = (const float*)d_in[9];
    const float* ln2_w    = (const float*)d_in[10];
    const float* ln2_b    = (const float*)d_in[11];
    const float* q_w      = (const float*)d_in[12];
    const float* q_b      = (const float*)d_in[13];
    const float* k_w      = (const float*)d_in[14];
    const float* k_b      = (const float*)d_in[15];
    const float* v_w      = (const float*)d_in[16];
    const float* v_b      = (const float*)d_in[17];
    const float* c_w      = (const float*)d_in[18];
    const float* c_b      = (const float*)d_in[19];
    const float* fc_w     = (const float*)d_in[20];
    const float* fc_b     = (const float*)d_in[21];
    const float* proj_w   = (const float*)d_in[22];
    const float* proj_b   = (const float*)d_in[23];
    float* out = (float*)d_out;

    float *p_x1;
    __half *p_qh, *p_kh, *p_vh, *p_xnh, *p_snh, *p_yh, *p_hh;
    __half *p_wq, *p_wk, *p_wv, *p_wc, *p_wfc, *p_wpr;
    cudaGetSymbolAddress((void**)&p_x1,  g_x1);
    cudaGetSymbolAddress((void**)&p_qh,  g_qh);
    cudaGetSymbolAddress((void**)&p_kh,  g_kh);
    cudaGetSymbolAddress((void**)&p_vh,  g_vh);
    cudaGetSymbolAddress((void**)&p_xnh, g_xnh);
    cudaGetSymbolAddress((void**)&p_snh, g_snh);
    cudaGetSymbolAddress((void**)&p_yh,  g_yh);
    cudaGetSymbolAddress((void**)&p_hh,  g_hh);
    cudaGetSymbolAddress((void**)&p_wq,  g_wq);
    cudaGetSymbolAddress((void**)&p_wk,  g_wk);
    cudaGetSymbolAddress((void**)&p_wv,  g_wv);
    cudaGetSymbolAddress((void**)&p_wc,  g_wc);
    cudaGetSymbolAddress((void**)&p_wfc, g_wfc);
    cudaGetSymbolAddress((void**)&p_wpr, g_wpr);

    const int WSQ = NE * NE, WFC = FCD * NE;
    dim3 g64 (NE / 128, NTOK / 64);    // MI=1 square GEMMs + proj: 6 x 64 = 384
    dim3 gfc (FCD / 128, NTOK / 128);  // MI=2 fc GEMM: 24 x 32 = 768
    dim3 ga  (LM / 64, NH, NB);
    dim3 gcv (WFC / 2048, 6);

    fuse_prep_kernel<<<NB, LS>>>(mod_idx, mod_age);                               // 0
    ln_kernel<<<NTOK, 256>>>(x, p_xnh, ln1_w, ln1_b);                             // 1
    f2h6_kernel<<<gcv, 256>>>(q_w, k_w, v_w, c_w, fc_w, proj_w,
                              p_wq, p_wk, p_wv, p_wc, p_wfc, p_wpr, WSQ, WFC);    // 2

    // 3: first GEMM (MI=1)  <-- ncu capture slot
    hgemm_kernel<3, 1><<<g64, 256>>>(p_xnh, p_wq, q_b, nullptr, p_qh, NTOK, NE, NE); // 3

    fuse_ln_kernel<<<NTOK, 256>>>(mod2, mod3, p_snh, ln0_w, ln0_b);               // 4
    hgemm_kernel<3, 1><<<g64, 256>>>(p_snh, p_wk, k_b, nullptr, p_kh, NTOK, NE, NE); // 5
    hgemm_kernel<3, 1><<<g64, 256>>>(p_snh, p_wv, v_b, nullptr, p_vh, NTOK, NE, NE); // 6

    attn_mma_kernel<<<ga, 128>>>(p_qh, p_kh, p_vh, age, mod_age, p_yh);           // 7

    hgemm_kernel<1, 1><<<g64, 256>>>(p_yh, p_wc, c_b, x, p_x1, NTOK, NE, NE);     // 8
    ln_kernel<<<NTOK, 256>>>(p_x1, p_xnh, ln2_w, ln2_b);                          // 9
    hgemm_kernel<2, 2><<<gfc, 256>>>(p_xnh, p_wfc, fc_b, nullptr, p_hh, NTOK, FCD, NE); // 10
    hgemm_kernel<1, 1><<<g64, 256>>>(p_hh, p_wpr, proj_b, p_x1, out, NTOK, NE, FCD);    // 11
}